// round 4
// baseline (speedup 1.0000x reference)
#include <cuda_runtime.h>
#include <math.h>

// ---------------- problem constants ----------------
namespace {
constexpr int Bc   = 2;
constexpr int Sc   = 1024;
constexpr int Dc   = 1024;
constexpr int NHc  = 8;
constexpr int QKc  = 512;   // qk proj width
constexpr int Vc   = 1024;  // v proj width
constexpr int DQKc = 64;    // per-head qk dim
constexpr int DHVc = 128;   // per-head v dim
}

// ---------------- scratch (device globals; no runtime alloc allowed) -------
__device__ float g_q     [Bc*Sc*QKc];   // pre-scaled q (q * DQK^-0.5)
__device__ float g_k     [Bc*Sc*QKc];
__device__ float g_v     [Bc*Sc*Vc];
__device__ float g_og    [Bc*Sc*Vc];
__device__ float g_h     [Bc*Sc*Vc];
__device__ float g_hout  [Bc*Sc*Vc];
__device__ float g_icap  [Bc*NHc*Sc];
__device__ float g_flog  [Bc*NHc*Sc];
__device__ float g_fact  [Bc*NHc*Sc];
__device__ float g_iact  [Bc*NHc*Sc];
__device__ float g_em    [Bc*NHc*Sc];   // exp(-m_t)
__device__ float g_invden[Bc*NHc*Sc];   // 1 / denom_t

// ---------------- 128x128x16 fp32 SGEMM tile (out = A[M,K] @ W[N,K]^T) -----
// K = Dc = 1024 fixed; A ld = Dc, W ld = Dc. 256 threads, 8x8 per thread.
__device__ __forceinline__ void sgemm_tile128(
    const float* __restrict__ A,
    const float* __restrict__ W,
    float* __restrict__ Cout,
    int ldc, int m0, int n0, float scale)
{
    __shared__ float As[16][132];
    __shared__ float Bs[16][132];
    const int tid = threadIdx.x;
    const int tx  = tid & 15;   // n
    const int ty  = tid >> 4;   // m
    float acc[8][8];
#pragma unroll
    for (int i = 0; i < 8; ++i)
#pragma unroll
        for (int j = 0; j < 8; ++j) acc[i][j] = 0.f;

    for (int kt = 0; kt < Dc; kt += 16) {
#pragma unroll
        for (int u = 0; u < 2; ++u) {
            int id  = tid + 256 * u;       // 512 float4 per tile
            int row = id >> 2;
            int c4  = id & 3;
            float4 a = *(const float4*)(A + (m0 + row) * Dc + kt + c4 * 4);
            float4 w = *(const float4*)(W + (n0 + row) * Dc + kt + c4 * 4);
            As[c4*4+0][row] = a.x; As[c4*4+1][row] = a.y;
            As[c4*4+2][row] = a.z; As[c4*4+3][row] = a.w;
            Bs[c4*4+0][row] = w.x; Bs[c4*4+1][row] = w.y;
            Bs[c4*4+2][row] = w.z; Bs[c4*4+3][row] = w.w;
        }
        __syncthreads();
#pragma unroll
        for (int kk = 0; kk < 16; ++kk) {
            float4 a0 = *(const float4*)&As[kk][ty*8];
            float4 a1 = *(const float4*)&As[kk][ty*8+4];
            float4 b0 = *(const float4*)&Bs[kk][tx*8];
            float4 b1 = *(const float4*)&Bs[kk][tx*8+4];
            float ra[8] = {a0.x,a0.y,a0.z,a0.w,a1.x,a1.y,a1.z,a1.w};
            float rb[8] = {b0.x,b0.y,b0.z,b0.w,b1.x,b1.y,b1.z,b1.w};
#pragma unroll
            for (int i = 0; i < 8; ++i)
#pragma unroll
                for (int j = 0; j < 8; ++j)
                    acc[i][j] = fmaf(ra[i], rb[j], acc[i][j]);
        }
        __syncthreads();
    }
#pragma unroll
    for (int i = 0; i < 8; ++i) {
        float* cp = Cout + (m0 + ty*8 + i) * ldc + n0 + tx*8;
        float4 o0 = make_float4(acc[i][0]*scale, acc[i][1]*scale,
                                acc[i][2]*scale, acc[i][3]*scale);
        float4 o1 = make_float4(acc[i][4]*scale, acc[i][5]*scale,
                                acc[i][6]*scale, acc[i][7]*scale);
        *(float4*)cp       = o0;
        *(float4*)(cp + 4) = o1;
    }
}

// Fused projection GEMM: blockIdx.x selects the weight segment.
// n-blocks: [0,4)=Wq -> g_q (scaled), [4,8)=Wk, [8,16)=Wv, [16,24)=Wog
__global__ __launch_bounds__(256, 2) void gemm_proj(
    const float* __restrict__ x,
    const float* __restrict__ Wq, const float* __restrict__ Wk,
    const float* __restrict__ Wv, const float* __restrict__ Wog)
{
    const int nb = blockIdx.x;
    const int m0 = blockIdx.y * 128;
    const float* W; float* C; int ldc; int n0; float scale = 1.f;
    if (nb < 4)       { W = Wq;  C = g_q;  ldc = QKc; n0 = nb * 128; scale = 0.125f; }
    else if (nb < 8)  { W = Wk;  C = g_k;  ldc = QKc; n0 = (nb-4)  * 128; }
    else if (nb < 16) { W = Wv;  C = g_v;  ldc = Vc;  n0 = (nb-8)  * 128; }
    else              { W = Wog; C = g_og; ldc = Vc;  n0 = (nb-16) * 128; }
    sgemm_tile128(x, W, C, ldc, m0, n0, scale);
}

// Output GEMM: y = h_out @ Wout^T
__global__ __launch_bounds__(256, 2) void gemm_out(
    const float* __restrict__ Wout, float* __restrict__ y)
{
    sgemm_tile128(g_hout, Wout, y, Dc, blockIdx.y * 128, blockIdx.x * 128, 1.f);
}

// ---------------- gate GEMV: i_pre/f_pre = softcap(x @ W^T + b) ------------
// one warp per (row, output); 2048 rows x 16 outputs = 32768 warps
__global__ void gates_kernel(const float* __restrict__ x,
                             const float* __restrict__ Wi, const float* __restrict__ bi,
                             const float* __restrict__ Wf, const float* __restrict__ bf)
{
    const int wid  = blockIdx.x * (blockDim.x >> 5) + (threadIdx.x >> 5);
    const int lane = threadIdx.x & 31;
    const int row  = wid >> 4;          // 0..2047
    const int o    = wid & 15;          // 0..15
    const int h    = o & 7;
    const bool isF = (o >= 8);
    const float* Wp = isF ? Wf : Wi;
    const float* bp = isF ? bf : bi;
    const float4* xr = (const float4*)(x  + (size_t)row * Dc);
    const float4* wr = (const float4*)(Wp + (size_t)h   * Dc);
    float acc = 0.f;
#pragma unroll
    for (int c = lane; c < Dc/4; c += 32) {
        float4 xv = __ldg(&xr[c]);
        float4 wv = __ldg(&wr[c]);
        acc += xv.x*wv.x + xv.y*wv.y + xv.z*wv.z + xv.w*wv.w;
    }
#pragma unroll
    for (int off = 16; off > 0; off >>= 1)
        acc += __shfl_xor_sync(0xffffffffu, acc, off);
    if (lane == 0) {
        float pre = acc + bp[h];
        float cap = 15.f * tanhf(pre * (1.f/15.f));
        int b = row >> 10, t = row & (Sc - 1);
        int idx = (b * NHc + h) * Sc + t;
        if (isF) {
            // stable log_sigmoid
            float fl = (cap >= 0.f) ? -log1pf(expf(-cap))
                                    : (cap - log1pf(expf(cap)));
            g_flog[idx] = fl;
        } else {
            g_icap[idx] = cap;
        }
    }
}

// ---------------- max-state scan + activations (per (b,h)) -----------------
__global__ void scan_kernel()
{
    __shared__ float sFl[Sc], sIc[Sc], sM[Sc];
    const int bh  = blockIdx.x;
    const int tid = threadIdx.x;
    const float* fl = g_flog + bh * Sc;
    const float* ic = g_icap + bh * Sc;
    for (int t = tid; t < Sc; t += blockDim.x) { sFl[t] = fl[t]; sIc[t] = ic[t]; }
    __syncthreads();
    if (tid == 0) {
        float m = 0.f;
#pragma unroll 8
        for (int t = 0; t < Sc; ++t) {
            m = fmaxf(sFl[t] + m, sIc[t]);
            sM[t] = m;
        }
    }
    __syncthreads();
    for (int t = tid; t < Sc; t += blockDim.x) {
        float m  = sM[t];
        float mp = (t > 0) ? sM[t-1] : 0.f;
        int idx  = bh * Sc + t;
        g_fact[idx] = expf(sFl[t] + mp - m);
        g_iact[idx] = expf(sIc[t] - m);
        g_em[idx]   = expf(-m);
    }
}

// ---------------- n-scan + denominator (one warp computes per (b,h)) -------
// warps 1..3 prefetch the next 32-step tile into SMEM while warp 0 scans.
__global__ void nscan_kernel()
{
    __shared__ float sK[2][32][64];
    __shared__ float sQ[2][32][64];
    __shared__ float sS[2][3][32];
    const int bh = blockIdx.x;
    const int b = bh >> 3, h = bh & 7;
    const int tid = threadIdx.x;
    const int warp = tid >> 5, lane = tid & 31;

    { // tile 0 loaded by all 128 threads
        for (int id = tid; id < 512; id += 128) {
            int r = id >> 4, c = id & 15;
            int gb = (b*Sc + r) * QKc + h * DQKc + c * 4;
            *(float4*)&sK[0][r][c*4] = *(const float4*)&g_k[gb];
            *(float4*)&sQ[0][r][c*4] = *(const float4*)&g_q[gb];
        }
        if (tid < 96) {
            int which = tid >> 5, s = tid & 31;
            const float* sp = (which == 0) ? g_fact : ((which == 1) ? g_iact : g_em);
            sS[0][which][s] = sp[bh*Sc + s];
        }
    }
    __syncthreads();

    float n0 = 0.f, n1 = 0.f;
    const int NT = Sc / 32;
    for (int tile = 0; tile < NT; ++tile) {
        const int cur = tile & 1;
        if (warp == 0) {
#pragma unroll 4
            for (int s = 0; s < 32; ++s) {
                float fa = sS[cur][0][s];
                float ia = sS[cur][1][s];
                float em = sS[cur][2][s];
                float2 kv = *(const float2*)&sK[cur][s][lane*2];
                float2 qv = *(const float2*)&sQ[cur][s][lane*2];
                n0 = fa*n0 + ia*kv.x;
                n1 = fa*n1 + ia*kv.y;
                float p = qv.x*n0 + qv.y*n1;
#pragma unroll
                for (int off = 16; off > 0; off >>= 1)
                    p += __shfl_xor_sync(0xffffffffu, p, off);
                if (lane == 0) {
                    float den = fmaxf(fabsf(p), em) + 1e-6f;
                    g_invden[bh*Sc + tile*32 + s] = 1.f / den;
                }
            }
        } else if (tile + 1 < NT) {
            const int nb_ = cur ^ 1;
            const int t0 = (tile + 1) * 32;
            for (int id = tid - 32; id < 512; id += 96) {
                int r = id >> 4, c = id & 15;
                int gb = (b*Sc + t0 + r) * QKc + h * DQKc + c * 4;
                *(float4*)&sK[nb_][r][c*4] = *(const float4*)&g_k[gb];
                *(float4*)&sQ[nb_][r][c*4] = *(const float4*)&g_q[gb];
            }
            int id2 = tid - 32;
            if (id2 < 96) {
                int which = id2 >> 5, s = id2 & 31;
                const float* sp = (which == 0) ? g_fact : ((which == 1) ? g_iact : g_em);
                sS[nb_][which][s] = sp[bh*Sc + t0 + s];
            }
        }
        __syncthreads();
    }
}

// ---------------- main C-state recurrence -----------------------------------
// grid (8 vblocks, 16 heads); block 128 = 16 v-cols x 8 d-slices.
// Each thread owns C[d0..d0+8, v] in registers; k/q/v staged via SMEM with
// register double-buffering of the next 32-step tile.
__global__ __launch_bounds__(128) void recur_kernel()
{
    __shared__ float sK[32][64];
    __shared__ float sQ[32][64];
    __shared__ float sV[32][16];
    __shared__ float sS[3][32];   // 0:f_act 1:i_act 2:inv_denom
    const int vb = blockIdx.x;            // 0..7
    const int bh = blockIdx.y;            // 0..15
    const int b = bh >> 3, h = bh & 7;
    const int tid = threadIdx.x;
    const int vi = tid >> 3;               // 0..15 (v within block)
    const int dc = tid & 7;                // 0..7  (d slice)

    float C[8];
#pragma unroll
    for (int j = 0; j < 8; ++j) C[j] = 0.f;

    float4 rk[4], rq[4], rv;
    float rs = 0.f;

    // --- load tile 0 into regs ---
    {
#pragma unroll
        for (int u = 0; u < 4; ++u) {
            int id = tid + 128*u;
            int r = id >> 4, c = id & 15;
            int gb = (b*Sc + r) * QKc + h * DQKc + c * 4;
            rk[u] = *(const float4*)&g_k[gb];
            rq[u] = *(const float4*)&g_q[gb];
        }
        { int r = tid >> 2, c = tid & 3;
          rv = *(const float4*)&g_v[(b*Sc + r) * Vc + h * DHVc + vb*16 + c*4]; }
        if (tid < 96) {
            int which = tid >> 5, s = tid & 31;
            const float* sp = (which == 0) ? g_fact : ((which == 1) ? g_iact : g_invden);
            rs = sp[bh*Sc + s];
        }
    }
    // commit tile 0
#pragma unroll
    for (int u = 0; u < 4; ++u) {
        int id = tid + 128*u;
        int r = id >> 4, c = id & 15;
        *(float4*)&sK[r][c*4] = rk[u];
        *(float4*)&sQ[r][c*4] = rq[u];
    }
    { int r = tid >> 2, c = tid & 3; *(float4*)&sV[r][c*4] = rv; }
    if (tid < 96) sS[tid>>5][tid&31] = rs;
    __syncthreads();

    const int NT = Sc / 32;
    for (int tile = 0; tile < NT; ++tile) {
        if (tile + 1 < NT) {             // issue next tile's global loads early
            const int t0 = (tile + 1) * 32;
#pragma unroll
            for (int u = 0; u < 4; ++u) {
                int id = tid + 128*u;
                int r = id >> 4, c = id & 15;
                int gb = (b*Sc + t0 + r) * QKc + h * DQKc + c * 4;
                rk[u] = *(const float4*)&g_k[gb];
                rq[u] = *(const float4*)&g_q[gb];
            }
            { int r = tid >> 2, c = tid & 3;
              rv = *(const float4*)&g_v[(b*Sc + t0 + r) * Vc + h * DHVc + vb*16 + c*4]; }
            if (tid < 96) {
                int which = tid >> 5, s = tid & 31;
                const float* sp = (which == 0) ? g_fact : ((which == 1) ? g_iact : g_invden);
                rs = sp[bh*Sc + t0 + s];
            }
        }
#pragma unroll 4
        for (int s = 0; s < 32; ++s) {
            float fa  = sS[0][s];
            float iv  = sS[1][s] * sV[s][vi];
            float idn = sS[2][s];
            float4 k0 = *(const float4*)&sK[s][dc*8];
            float4 k1 = *(const float4*)&sK[s][dc*8+4];
            float4 q0 = *(const float4*)&sQ[s][dc*8];
            float4 q1 = *(const float4*)&sQ[s][dc*8+4];
            C[0] = fa*C[0] + k0.x*iv;
            C[1] = fa*C[1] + k0.y*iv;
            C[2] = fa*C[2] + k0.z*iv;
            C[3] = fa*C[3] + k0.w*iv;
            C[4] = fa*C[4] + k1.x*iv;
            C[5] = fa*C[5] + k1.y*iv;
            C[6] = fa*C[6] + k1.z*iv;
            C[7] = fa*C[7] + k1.w*iv;
            float p0 = q0.x*C[0] + q0.y*C[1] + q0.z*C[2] + q0.w*C[3];
            float p1 = q1.x*C[4] + q1.y*C[5] + q1.z*C[6] + q1.w*C[7];
            float p = p0 + p1;
            p += __shfl_xor_sync(0xffffffffu, p, 1);
            p += __shfl_xor_sync(0xffffffffu, p, 2);
            p += __shfl_xor_sync(0xffffffffu, p, 4);
            if (dc == 0) {
                int t = tile*32 + s;
                g_h[(b*Sc + t) * Vc + h*DHVc + vb*16 + vi] = p * idn;
            }
        }
        if (tile + 1 < NT) {
            __syncthreads();             // everyone done reading current tile
#pragma unroll
            for (int u = 0; u < 4; ++u) {
                int id = tid + 128*u;
                int r = id >> 4, c = id & 15;
                *(float4*)&sK[r][c*4] = rk[u];
                *(float4*)&sQ[r][c*4] = rq[u];
            }
            { int r = tid >> 2, c = tid & 3; *(float4*)&sV[r][c*4] = rv; }
            if (tid < 96) sS[tid>>5][tid&31] = rs;
            __syncthreads();
        }
    }
}

// ---------------- per-head layernorm * gamma * sigmoid(o_pre) --------------
__global__ void ln_gate_kernel(const float* __restrict__ gamma)
{
    const int row  = blockIdx.x;           // b*S + s
    const int hd   = threadIdx.x >> 5;     // head 0..7 (one warp per head)
    const int lane = threadIdx.x & 31;
    const int base = row * Vc + hd * DHVc + lane * 4;
    float4 hv = *(const float4*)&g_h[base];
    float sm = hv.x + hv.y + hv.z + hv.w;
#pragma unroll
    for (int off = 16; off > 0; off >>= 1)
        sm += __shfl_xor_sync(0xffffffffu, sm, off);
    float mu = sm * (1.f/128.f);
    float dx = hv.x - mu, dy = hv.y - mu, dz = hv.z - mu, dw = hv.w - mu;
    float sq = dx*dx + dy*dy + dz*dz + dw*dw;
#pragma unroll
    for (int off = 16; off > 0; off >>= 1)
        sq += __shfl_xor_sync(0xffffffffu, sq, off);
    float rstd = rsqrtf(sq * (1.f/128.f) + 1e-6f);
    float4 gm = *(const float4*)&gamma[hd * DHVc + lane * 4];
    float4 og = *(const float4*)&g_og[base];
    float4 o;
    o.x = dx * rstd * gm.x / (1.f + expf(-og.x));
    o.y = dy * rstd * gm.y / (1.f + expf(-og.y));
    o.z = dz * rstd * gm.z / (1.f + expf(-og.z));
    o.w = dw * rstd * gm.w / (1.f + expf(-og.w));
    *(float4*)&g_hout[base] = o;
}

// ---------------- launch ----------------------------------------------------
extern "C" void kernel_launch(void* const* d_in, const int* in_sizes, int n_in,
                              void* d_out, int out_size)
{
    const float* x     = (const float*)d_in[0];
    const float* Wq    = (const float*)d_in[1];
    const float* Wk    = (const float*)d_in[2];
    const float* Wv    = (const float*)d_in[3];
    const float* Wog   = (const float*)d_in[4];
    const float* Wi    = (const float*)d_in[5];
    const float* bi    = (const float*)d_in[6];
    const float* Wf    = (const float*)d_in[7];
    const float* bf    = (const float*)d_in[8];
    const float* gamma = (const float*)d_in[9];
    const float* Wout  = (const float*)d_in[10];
    float* y = (float*)d_out;

    // q,k,v,og projections (q pre-scaled by DQK^-0.5 in epilogue)
    gemm_proj<<<dim3(24, 16), 256>>>(x, Wq, Wk, Wv, Wog);
    // i/f gate pre-activations (softcap, log_sigmoid)
    gates_kernel<<<4096, 256>>>(x, Wi, bi, Wf, bf);
    // max-state scan + f_act/i_act/exp(-m)
    scan_kernel<<<16, 128>>>();
    // n recurrence + denominators
    nscan_kernel<<<16, 128>>>();
    // main C recurrence -> h
    recur_kernel<<<dim3(8, 16), 128>>>();
    // per-head layernorm * gamma * sigmoid(o_pre)
    ln_gate_kernel<<<Bc * Sc, 256>>>(gamma);
    // y = h_out @ Wout^T
    gemm_out<<<dim3(8, 16), 256>>>(Wout, y);
}

// round 6
// speedup vs baseline: 1.4708x; 1.4708x over previous
#include <cuda_runtime.h>
#include <cuda_bf16.h>
#include <math.h>
#include <stdint.h>

// ---------------- problem constants ----------------
namespace {
constexpr int Bc   = 2;
constexpr int Sc   = 1024;
constexpr int Dc   = 1024;
constexpr int NHc  = 8;
constexpr int QKc  = 512;
constexpr int Vc   = 1024;
constexpr int DQKc = 64;
constexpr int DHVc = 128;
constexpr int KB2  = 2048;   // bf16 hi|lo split row width (hi: [0,1024), lo: [1024,2048))
}

// ---------------- scratch (device globals; no runtime alloc allowed) -------
__device__ float g_q     [Bc*Sc*QKc];   // pre-scaled q
__device__ float g_k     [Bc*Sc*QKc];
__device__ float g_v     [Bc*Sc*Vc];
__device__ float g_og    [Bc*Sc*Vc];
__device__ float g_h     [Bc*Sc*Vc];
__device__ float g_icap  [Bc*NHc*Sc];
__device__ float g_flog  [Bc*NHc*Sc];
__device__ float g_fact  [Bc*NHc*Sc];
__device__ float g_iact  [Bc*NHc*Sc];
__device__ float g_em    [Bc*NHc*Sc];
__device__ float g_invden[Bc*NHc*Sc];

// bf16 hi/lo split operands
__device__ __nv_bfloat16 g_xb   [Bc*Sc*KB2];      // x split
__device__ __nv_bfloat16 g_Wb   [3072*KB2];       // [Wq;Wk;Wv;Wog] split
__device__ __nv_bfloat16 g_Woutb[Dc*KB2];         // Wout split
__device__ __nv_bfloat16 g_houtb[Bc*Sc*KB2];      // gated/normed h split

// ---------------- mma.sync helpers (baseline sm_80+ path) ------------------
__device__ __forceinline__ uint32_t s2u(const void* p) {
    return (uint32_t)__cvta_generic_to_shared(p);
}
__device__ __forceinline__ void cp16(uint32_t saddr, const void* g) {
    asm volatile("cp.async.cg.shared.global [%0], [%1], 16;"
                 :: "r"(saddr), "l"(g) : "memory");
}
__device__ __forceinline__ void cp_commit() {
    asm volatile("cp.async.commit_group;" ::: "memory");
}
template <int N>
__device__ __forceinline__ void cp_wait() {
    asm volatile("cp.async.wait_group %0;" :: "n"(N) : "memory");
}
__device__ __forceinline__ void ldsm_x4(uint32_t* r, uint32_t addr) {
    asm volatile("ldmatrix.sync.aligned.m8n8.x4.shared.b16 {%0,%1,%2,%3}, [%4];"
                 : "=r"(r[0]), "=r"(r[1]), "=r"(r[2]), "=r"(r[3]) : "r"(addr));
}
__device__ __forceinline__ void mma16816(float* d, const uint32_t* a, const uint32_t* b) {
    asm volatile(
        "mma.sync.aligned.m16n8k16.row.col.f32.bf16.bf16.f32 "
        "{%0,%1,%2,%3}, {%4,%5,%6,%7}, {%8,%9}, {%0,%1,%2,%3};"
        : "+f"(d[0]), "+f"(d[1]), "+f"(d[2]), "+f"(d[3])
        : "r"(a[0]), "r"(a[1]), "r"(a[2]), "r"(a[3]), "r"(b[0]), "r"(b[1]));
}

// ---------------- 128x128 bf16 mma.sync GEMM tile, 3-term split K ----------
// A: [M rows][2048] bf16 (hi|lo), B: [N rows][2048] bf16 (hi|lo).
// Computes fp32 D = Ah@Bh^T + Al@Bh^T + Ah@Bl^T  (error-compensated fp32-ish).
// C points at output element (row0, col0); ldc in floats.
// Block: 256 threads = 8 warps (2m x 4n), warp tile 64x32, BK=32 double-buffered.
__device__ __forceinline__ void mma_gemm_tile(
    const __nv_bfloat16* __restrict__ A,
    const __nv_bfloat16* __restrict__ B,
    float* __restrict__ C, int ldc, float scale)
{
    __shared__ __align__(128) __nv_bfloat16 sA[2][128 * 32];
    __shared__ __align__(128) __nv_bfloat16 sB[2][128 * 32];

    const int tid  = threadIdx.x;
    const int wid  = tid >> 5, lane = tid & 31;
    const int wm   = (wid & 1) * 64;     // warp m-offset
    const int wn   = (wid >> 1) * 32;    // warp n-offset

    float acc[4][4][4];
#pragma unroll
    for (int i = 0; i < 4; ++i)
#pragma unroll
        for (int j = 0; j < 4; ++j)
#pragma unroll
            for (int q = 0; q < 4; ++q) acc[i][j][q] = 0.f;

    // per-thread gmem load coords: 512 x 16B per operand per chunk
    const int lrow = tid >> 2;          // 0..63 (+64 on second pass)
    const int lc   = tid & 3;           // 16B chunk within 64B row
    // per-thread ldmatrix smem addresses (within a buffer)
    // A fragment: rows wm + im*16 + (lane&15), byte col = ks*32 + ((lane>>4)&1)*16
    // B fragment: rows wn + ib*16 + (lane&7) + ((lane>>4)&1)*8, byte col = ks*32 + ((lane>>3)&1)*16

    const int NCH = 96;                 // 3 terms x 32 chunks of K=32
    auto chunk_offs = [] (int cidx, int& a_k, int& b_k) {
        int term = cidx >> 5, kk = cidx & 31;
        a_k = (term == 1 ? 1024 : 0) + kk * 32;
        b_k = (term == 2 ? 1024 : 0) + kk * 32;
    };

    // prologue: load chunk 0 into buf 0
    {
        int a_k, b_k; chunk_offs(0, a_k, b_k);
#pragma unroll
        for (int u = 0; u < 2; ++u) {
            int row = lrow + 64 * u;
            int pc  = lc ^ ((row >> 1) & 3);
            cp16(s2u(&sA[0][row * 32 + pc * 8]), A + (size_t)row * KB2 + a_k + lc * 8);
            cp16(s2u(&sB[0][row * 32 + pc * 8]), B + (size_t)row * KB2 + b_k + lc * 8);
        }
        cp_commit();
    }

    for (int c = 0; c < NCH; ++c) {
        const int buf = c & 1;
        if (c + 1 < NCH) {
            int a_k, b_k; chunk_offs(c + 1, a_k, b_k);
            const int nb = buf ^ 1;
#pragma unroll
            for (int u = 0; u < 2; ++u) {
                int row = lrow + 64 * u;
                int pc  = lc ^ ((row >> 1) & 3);
                cp16(s2u(&sA[nb][row * 32 + pc * 8]), A + (size_t)row * KB2 + a_k + lc * 8);
                cp16(s2u(&sB[nb][row * 32 + pc * 8]), B + (size_t)row * KB2 + b_k + lc * 8);
            }
            cp_commit();
            cp_wait<1>();
        } else {
            cp_wait<0>();
        }
        __syncthreads();

#pragma unroll
        for (int ks = 0; ks < 2; ++ks) {
            uint32_t af[4][4];
#pragma unroll
            for (int im = 0; im < 4; ++im) {
                int row = wm + im * 16 + (lane & 15);
                int ch  = ks * 2 + ((lane >> 4) & 1);
                int pc  = ch ^ ((row >> 1) & 3);
                ldsm_x4(af[im], s2u(&sA[buf][row * 32 + pc * 8]));
            }
            uint32_t bfr[2][4];
#pragma unroll
            for (int ib = 0; ib < 2; ++ib) {
                int row = wn + ib * 16 + (lane & 7) + ((lane >> 4) & 1) * 8;
                int ch  = ks * 2 + ((lane >> 3) & 1);
                int pc  = ch ^ ((row >> 1) & 3);
                ldsm_x4(bfr[ib], s2u(&sB[buf][row * 32 + pc * 8]));
            }
#pragma unroll
            for (int im = 0; im < 4; ++im)
#pragma unroll
                for (int in = 0; in < 4; ++in)
                    mma16816(acc[im][in], af[im], &bfr[in >> 1][(in & 1) * 2]);
        }
        __syncthreads();
    }

    // epilogue
    const int group = lane >> 2, tg = lane & 3;
#pragma unroll
    for (int im = 0; im < 4; ++im) {
        int r0 = wm + im * 16 + group;
#pragma unroll
        for (int half = 0; half < 2; ++half) {
            float* crow = C + (size_t)(r0 + half * 8) * ldc;
#pragma unroll
            for (int in = 0; in < 4; ++in) {
                float2 v = make_float2(acc[im][in][half * 2]     * scale,
                                       acc[im][in][half * 2 + 1] * scale);
                *(float2*)(crow + wn + in * 8 + tg * 2) = v;
            }
        }
    }
}

// proj: n-tiles 0..3 -> q (scaled), 4..7 -> k, 8..15 -> v, 16..23 -> og
__global__ __launch_bounds__(256, 2) void gemm_proj_tc()
{
    const int nt = blockIdx.x;
    const int m0 = blockIdx.y * 128;
    float* Cp; int ldc, n0; float scale = 1.f;
    if (nt < 4)       { Cp = g_q;  ldc = QKc; n0 = nt * 128;        scale = 0.125f; }
    else if (nt < 8)  { Cp = g_k;  ldc = QKc; n0 = (nt - 4)  * 128; }
    else if (nt < 16) { Cp = g_v;  ldc = Vc;  n0 = (nt - 8)  * 128; }
    else              { Cp = g_og; ldc = Vc;  n0 = (nt - 16) * 128; }
    mma_gemm_tile(g_xb + (size_t)m0 * KB2,
                  g_Wb + (size_t)nt * 128 * KB2,
                  Cp + (size_t)m0 * ldc + n0, ldc, scale);
}

__global__ __launch_bounds__(256, 2) void gemm_out_tc(float* __restrict__ y)
{
    const int n0 = blockIdx.x * 128;
    const int m0 = blockIdx.y * 128;
    mma_gemm_tile(g_houtb + (size_t)m0 * KB2,
                  g_Woutb + (size_t)n0 * KB2,
                  y + (size_t)m0 * Dc + n0, Dc, 1.f);
}

// ---------------- fp32 -> bf16 hi/lo split conversion ----------------------
__device__ __forceinline__ void split2(float v, __nv_bfloat16& h, __nv_bfloat16& l) {
    h = __float2bfloat16(v);
    l = __float2bfloat16(v - __bfloat162float(h));
}
__global__ void cvt_pair(const float* __restrict__ src,
                         __nv_bfloat16* __restrict__ dst, int total4)
{
    int idx = blockIdx.x * 256 + threadIdx.x;
    if (idx >= total4) return;
    int row = idx >> 8;       // 256 float4 per 1024-wide row
    int c4  = idx & 255;
    float4 v = ((const float4*)src)[idx];
    __nv_bfloat16 h0,h1,h2,h3,l0,l1,l2,l3;
    split2(v.x,h0,l0); split2(v.y,h1,l1); split2(v.z,h2,l2); split2(v.w,h3,l3);
    __nv_bfloat162* dh = (__nv_bfloat162*)(dst + (size_t)row * KB2 + c4 * 4);
    dh[0] = __halves2bfloat162(h0, h1);
    dh[1] = __halves2bfloat162(h2, h3);
    __nv_bfloat162* dl = (__nv_bfloat162*)(dst + (size_t)row * KB2 + 1024 + c4 * 4);
    dl[0] = __halves2bfloat162(l0, l1);
    dl[1] = __halves2bfloat162(l2, l3);
}

// ---------------- gate GEMV: i_pre/f_pre = softcap(x @ W^T + b) ------------
__global__ void gates_kernel(const float* __restrict__ x,
                             const float* __restrict__ Wi, const float* __restrict__ bi,
                             const float* __restrict__ Wf, const float* __restrict__ bf)
{
    const int wid  = blockIdx.x * (blockDim.x >> 5) + (threadIdx.x >> 5);
    const int lane = threadIdx.x & 31;
    const int row  = wid >> 4;
    const int o    = wid & 15;
    const int h    = o & 7;
    const bool isF = (o >= 8);
    const float* Wp = isF ? Wf : Wi;
    const float* bp = isF ? bf : bi;
    const float4* xr = (const float4*)(x  + (size_t)row * Dc);
    const float4* wr = (const float4*)(Wp + (size_t)h   * Dc);
    float acc = 0.f;
#pragma unroll
    for (int c = lane; c < Dc/4; c += 32) {
        float4 xv = __ldg(&xr[c]);
        float4 wv = __ldg(&wr[c]);
        acc += xv.x*wv.x + xv.y*wv.y + xv.z*wv.z + xv.w*wv.w;
    }
#pragma unroll
    for (int off = 16; off > 0; off >>= 1)
        acc += __shfl_xor_sync(0xffffffffu, acc, off);
    if (lane == 0) {
        float pre = acc + bp[h];
        float cap = 15.f * tanhf(pre * (1.f/15.f));
        int b = row >> 10, t = row & (Sc - 1);
        int idx = (b * NHc + h) * Sc + t;
        if (isF) {
            float fl = (cap >= 0.f) ? -log1pf(expf(-cap))
                                    : (cap - log1pf(expf(cap)));
            g_flog[idx] = fl;
        } else {
            g_icap[idx] = cap;
        }
    }
}

// ---------------- max-state scan + activations (per (b,h)) -----------------
__global__ void scan_kernel()
{
    __shared__ float sFl[Sc], sIc[Sc], sM[Sc];
    const int bh  = blockIdx.x;
    const int tid = threadIdx.x;
    const float* fl = g_flog + bh * Sc;
    const float* ic = g_icap + bh * Sc;
    for (int t = tid; t < Sc; t += blockDim.x) { sFl[t] = fl[t]; sIc[t] = ic[t]; }
    __syncthreads();
    if (tid == 0) {
        float m = 0.f;
#pragma unroll 8
        for (int t = 0; t < Sc; ++t) {
            m = fmaxf(sFl[t] + m, sIc[t]);
            sM[t] = m;
        }
    }
    __syncthreads();
    for (int t = tid; t < Sc; t += blockDim.x) {
        float m  = sM[t];
        float mp = (t > 0) ? sM[t-1] : 0.f;
        int idx  = bh * Sc + t;
        g_fact[idx] = expf(sFl[t] + mp - m);
        g_iact[idx] = expf(sIc[t] - m);
        g_em[idx]   = expf(-m);
    }
}

// ---------------- n-scan + denominator: one channel per thread -------------
__global__ __launch_bounds__(64) void nscan_kernel()
{
    __shared__ float sP[32][65];
    const int bh = blockIdx.x;
    const int b = bh >> 3, h = bh & 7;
    const int d = threadIdx.x;
    const int warp = d >> 5, lane = d & 31;
    const float* kp = g_k + (size_t)b*Sc*QKc + h*DQKc + d;
    const float* qp = g_q + (size_t)b*Sc*QKc + h*DQKc + d;
    const float* fa = g_fact + bh*Sc;
    const float* ia = g_iact + bh*Sc;
    float n = 0.f;
    for (int tile = 0; tile < Sc/32; ++tile) {
        const int t0 = tile * 32;
#pragma unroll 8
        for (int s = 0; s < 32; ++s) {
            int t = t0 + s;
            float kv = __ldg(kp + (size_t)t * QKc);
            float qv = __ldg(qp + (size_t)t * QKc);
            n = fa[t]*n + ia[t]*kv;
            sP[s][d] = qv * n;
        }
        __syncthreads();
#pragma unroll
        for (int i = 0; i < 16; ++i) {
            int tt = warp * 16 + i;
            float v = sP[tt][lane] + sP[tt][lane + 32];
#pragma unroll
            for (int off = 16; off > 0; off >>= 1)
                v += __shfl_xor_sync(0xffffffffu, v, off);
            if (lane == 0) {
                int t = t0 + tt;
                float den = fmaxf(fabsf(v), g_em[bh*Sc + t]) + 1e-6f;
                g_invden[bh*Sc + t] = 1.f / den;
            }
        }
        __syncthreads();
    }
}

// ---------------- main C-state recurrence -----------------------------------
__global__ __launch_bounds__(128) void recur_kernel()
{
    __shared__ float sK[32][64];
    __shared__ float sQ[32][64];
    __shared__ float sV[32][16];
    __shared__ float sS[3][32];
    const int vb = blockIdx.x;
    const int bh = blockIdx.y;
    const int b = bh >> 3, h = bh & 7;
    const int tid = threadIdx.x;
    const int vi = tid >> 3;
    const int dc = tid & 7;

    float C[8];
#pragma unroll
    for (int j = 0; j < 8; ++j) C[j] = 0.f;

    float4 rk[4], rq[4], rv;
    float rs = 0.f;

    {
#pragma unroll
        for (int u = 0; u < 4; ++u) {
            int id = tid + 128*u;
            int r = id >> 4, c = id & 15;
            int gb = (b*Sc + r) * QKc + h * DQKc + c * 4;
            rk[u] = *(const float4*)&g_k[gb];
            rq[u] = *(const float4*)&g_q[gb];
        }
        { int r = tid >> 2, c = tid & 3;
          rv = *(const float4*)&g_v[(b*Sc + r) * Vc + h * DHVc + vb*16 + c*4]; }
        if (tid < 96) {
            int which = tid >> 5, s = tid & 31;
            const float* sp = (which == 0) ? g_fact : ((which == 1) ? g_iact : g_invden);
            rs = sp[bh*Sc + s];
        }
    }
#pragma unroll
    for (int u = 0; u < 4; ++u) {
        int id = tid + 128*u;
        int r = id >> 4, c = id & 15;
        *(float4*)&sK[r][c*4] = rk[u];
        *(float4*)&sQ[r][c*4] = rq[u];
    }
    { int r = tid >> 2, c = tid & 3; *(float4*)&sV[r][c*4] = rv; }
    if (tid < 96) sS[tid>>5][tid&31] = rs;
    __syncthreads();

    const int NT = Sc / 32;
    for (int tile = 0; tile < NT; ++tile) {
        if (tile + 1 < NT) {
            const int t0 = (tile + 1) * 32;
#pragma unroll
            for (int u = 0; u < 4; ++u) {
                int id = tid + 128*u;
                int r = id >> 4, c = id & 15;
                int gb = (b*Sc + t0 + r) * QKc + h * DQKc + c * 4;
                rk[u] = *(const float4*)&g_k[gb];
                rq[u] = *(const float4*)&g_q[gb];
            }
            { int r = tid >> 2, c = tid & 3;
              rv = *(const float4*)&g_v[(b*Sc + t0 + r) * Vc + h * DHVc + vb*16 + c*4]; }
            if (tid < 96) {
                int which = tid >> 5, s = tid & 31;
                const float* sp = (which == 0) ? g_fact : ((which == 1) ? g_iact : g_invden);
                rs = sp[bh*Sc + t0 + s];
            }
        }
#pragma unroll 4
        for (int s = 0; s < 32; ++s) {
            float fa  = sS[0][s];
            float iv  = sS[1][s] * sV[s][vi];
            float idn = sS[2][s];
            float4 k0 = *(const float4*)&sK[s][dc*8];
            float4 k1 = *(const float4*)&sK[s][dc*8+4];
            float4 q0 = *(const float4*)&sQ[s][dc*8];
            float4 q1 = *(const float4*)&sQ[s][dc*8+4];
            C[0] = fa*C[0] + k0.x*iv;
            C[1] = fa*C[1] + k0.y*iv;
            C[2] = fa*C[2] + k0.z*iv;
            C[3] = fa*C[3] + k0.w*iv;
            C[4] = fa*C[4] + k1.x*iv;
            C[5] = fa*C[5] + k1.y*iv;
            C[6] = fa*C[6] + k1.z*iv;
            C[7] = fa*C[7] + k1.w*iv;
            float p0 = q0.x*C[0] + q0.y*C[1] + q0.z*C[2] + q0.w*C[3];
            float p1 = q1.x*C[4] + q1.y*C[5] + q1.z*C[6] + q1.w*C[7];
            float p = p0 + p1;
            p += __shfl_xor_sync(0xffffffffu, p, 1);
            p += __shfl_xor_sync(0xffffffffu, p, 2);
            p += __shfl_xor_sync(0xffffffffu, p, 4);
            if (dc == 0) {
                int t = tile*32 + s;
                g_h[(b*Sc + t) * Vc + h*DHVc + vb*16 + vi] = p * idn;
            }
        }
        if (tile + 1 < NT) {
            __syncthreads();
#pragma unroll
            for (int u = 0; u < 4; ++u) {
                int id = tid + 128*u;
                int r = id >> 4, c = id & 15;
                *(float4*)&sK[r][c*4] = rk[u];
                *(float4*)&sQ[r][c*4] = rq[u];
            }
            { int r = tid >> 2, c = tid & 3; *(float4*)&sV[r][c*4] = rv; }
            if (tid < 96) sS[tid>>5][tid&31] = rs;
            __syncthreads();
        }
    }
}

// ------ per-head layernorm * gamma * sigmoid(o_pre) -> bf16 hi/lo pairs ----
__global__ void ln_gate_kernel(const float* __restrict__ gamma)
{
    const int row  = blockIdx.x;           // b*S + s
    const int hd   = threadIdx.x >> 5;
    const int lane = threadIdx.x & 31;
    const int base = row * Vc + hd * DHVc + lane * 4;
    float4 hv = *(const float4*)&g_h[base];
    float sm = hv.x + hv.y + hv.z + hv.w;
#pragma unroll
    for (int off = 16; off > 0; off >>= 1)
        sm += __shfl_xor_sync(0xffffffffu, sm, off);
    float mu = sm * (1.f/128.f);
    float dx = hv.x - mu, dy = hv.y - mu, dz = hv.z - mu, dw = hv.w - mu;
    float sq = dx*dx + dy*dy + dz*dz + dw*dw;
#pragma unroll
    for (int off = 16; off > 0; off >>= 1)
        sq += __shfl_xor_sync(0xffffffffu, sq, off);
    float rstd = rsqrtf(sq * (1.f/128.f) + 1e-6f);
    float4 gm = *(const float4*)&gamma[hd * DHVc + lane * 4];
    float4 og = *(const float4*)&g_og[base];
    float ox = dx * rstd * gm.x / (1.f + expf(-og.x));
    float oy = dy * rstd * gm.y / (1.f + expf(-og.y));
    float oz = dz * rstd * gm.z / (1.f + expf(-og.z));
    float ow = dw * rstd * gm.w / (1.f + expf(-og.w));
    __nv_bfloat16 h0,h1,h2,h3,l0,l1,l2,l3;
    split2(ox,h0,l0); split2(oy,h1,l1); split2(oz,h2,l2); split2(ow,h3,l3);
    const int col = hd * DHVc + lane * 4;
    __nv_bfloat162* dh = (__nv_bfloat162*)(g_houtb + (size_t)row * KB2 + col);
    dh[0] = __halves2bfloat162(h0, h1);
    dh[1] = __halves2bfloat162(h2, h3);
    __nv_bfloat162* dl = (__nv_bfloat162*)(g_houtb + (size_t)row * KB2 + 1024 + col);
    dl[0] = __halves2bfloat162(l0, l1);
    dl[1] = __halves2bfloat162(l2, l3);
}

// ---------------- launch ----------------------------------------------------
extern "C" void kernel_launch(void* const* d_in, const int* in_sizes, int n_in,
                              void* d_out, int out_size)
{
    const float* x     = (const float*)d_in[0];
    const float* Wq    = (const float*)d_in[1];
    const float* Wk    = (const float*)d_in[2];
    const float* Wv    = (const float*)d_in[3];
    const float* Wog   = (const float*)d_in[4];
    const float* Wi    = (const float*)d_in[5];
    const float* bi    = (const float*)d_in[6];
    const float* Wf    = (const float*)d_in[7];
    const float* bf    = (const float*)d_in[8];
    const float* gamma = (const float*)d_in[9];
    const float* Wout  = (const float*)d_in[10];
    float* y = (float*)d_out;

    __nv_bfloat16* xb = nullptr; __nv_bfloat16* Wb = nullptr; __nv_bfloat16* Woutb = nullptr;
    cudaGetSymbolAddress((void**)&xb,    g_xb);
    cudaGetSymbolAddress((void**)&Wb,    g_Wb);
    cudaGetSymbolAddress((void**)&Woutb, g_Woutb);

    // fp32 -> bf16 hi/lo splits
    cvt_pair<<<2048, 256>>>(x,    xb,              2048*256);
    cvt_pair<<< 512, 256>>>(Wq,   Wb,               512*256);
    cvt_pair<<< 512, 256>>>(Wk,   Wb +  512*KB2,    512*256);
    cvt_pair<<<1024, 256>>>(Wv,   Wb + 1024*KB2,   1024*256);
    cvt_pair<<<1024, 256>>>(Wog,  Wb + 2048*KB2,   1024*256);
    cvt_pair<<<1024, 256>>>(Wout, Woutb,           1024*256);

    // q,k,v,og projections on tensor cores (mma.sync, 3-term bf16 split)
    gemm_proj_tc<<<dim3(24, 16), 256>>>();
    // i/f gate pre-activations (fp32 exact)
    gates_kernel<<<4096, 256>>>(x, Wi, bi, Wf, bf);
    // max-state scan
    scan_kernel<<<16, 128>>>();
    // n recurrence + denominators (channel-parallel)
    nscan_kernel<<<16, 64>>>();
    // main C recurrence -> h
    recur_kernel<<<dim3(8, 16), 128>>>();
    // layernorm * gamma * sigmoid(og) -> bf16 split
    ln_gate_kernel<<<Bc * Sc, 256>>>(gamma);
    // y = h_out @ Wout^T on tensor cores
    gemm_out_tc<<<dim3(8, 16), 256>>>(y);
}

// round 7
// speedup vs baseline: 1.5561x; 1.0580x over previous
#include <cuda_runtime.h>
#include <cuda_bf16.h>
#include <math.h>
#include <stdint.h>

// ---------------- problem constants ----------------
namespace {
constexpr int Bc   = 2;
constexpr int Sc   = 1024;
constexpr int Dc   = 1024;
constexpr int NHc  = 8;
constexpr int QKc  = 512;
constexpr int Vc   = 1024;
constexpr int DQKc = 64;
constexpr int DHVc = 128;
constexpr int KB2  = 2048;   // bf16 hi|lo split row width (hi: [0,1024), lo: [1024,2048))
}

// ---------------- scratch (device globals; no runtime alloc allowed) -------
__device__ float g_q     [Bc*Sc*QKc];   // pre-scaled q
__device__ float g_k     [Bc*Sc*QKc];
__device__ float g_v     [Bc*Sc*Vc];
__device__ float g_og    [Bc*Sc*Vc];
__device__ float g_h     [Bc*Sc*Vc];
__device__ float g_icap  [Bc*NHc*Sc];
__device__ float g_flog  [Bc*NHc*Sc];
__device__ float g_fact  [Bc*NHc*Sc];
__device__ float g_iact  [Bc*NHc*Sc];
__device__ float g_em    [Bc*NHc*Sc];
__device__ float g_invden[Bc*NHc*Sc];

// bf16 hi/lo split operands
__device__ __nv_bfloat16 g_xb   [Bc*Sc*KB2];
__device__ __nv_bfloat16 g_Wb   [3072*KB2];       // [Wq;Wk;Wv;Wog]
__device__ __nv_bfloat16 g_Woutb[Dc*KB2];
__device__ __nv_bfloat16 g_houtb[Bc*Sc*KB2];

// ---------------- mma.sync helpers -----------------------------------------
__device__ __forceinline__ uint32_t s2u(const void* p) {
    return (uint32_t)__cvta_generic_to_shared(p);
}
__device__ __forceinline__ void cp16(uint32_t saddr, const void* g) {
    asm volatile("cp.async.cg.shared.global [%0], [%1], 16;"
                 :: "r"(saddr), "l"(g) : "memory");
}
__device__ __forceinline__ void cp_commit() {
    asm volatile("cp.async.commit_group;" ::: "memory");
}
template <int N>
__device__ __forceinline__ void cp_wait() {
    asm volatile("cp.async.wait_group %0;" :: "n"(N) : "memory");
}
__device__ __forceinline__ void ldsm_x4(uint32_t* r, uint32_t addr) {
    asm volatile("ldmatrix.sync.aligned.m8n8.x4.shared.b16 {%0,%1,%2,%3}, [%4];"
                 : "=r"(r[0]), "=r"(r[1]), "=r"(r[2]), "=r"(r[3]) : "r"(addr));
}
__device__ __forceinline__ void mma16816(float* d, const uint32_t* a, const uint32_t* b) {
    asm volatile(
        "mma.sync.aligned.m16n8k16.row.col.f32.bf16.bf16.f32 "
        "{%0,%1,%2,%3}, {%4,%5,%6,%7}, {%8,%9}, {%0,%1,%2,%3};"
        : "+f"(d[0]), "+f"(d[1]), "+f"(d[2]), "+f"(d[3])
        : "r"(a[0]), "r"(a[1]), "r"(a[2]), "r"(a[3]), "r"(b[0]), "r"(b[1]));
}

// ---------------- 128x128 bf16 mma.sync GEMM tile, 3-term split K ----------
// D = Ah@Bh^T + Al@Bh^T + Ah@Bl^T  (fp32 accumulate).
// 256 threads = 8 warps (2m x 4n), warp tile 64x32, BK=32, 3-stage pipeline.
__device__ __forceinline__ void mma_gemm_tile(
    const __nv_bfloat16* __restrict__ A,
    const __nv_bfloat16* __restrict__ B,
    float* __restrict__ C, int ldc, float scale)
{
    __shared__ __align__(128) __nv_bfloat16 sA[3][128 * 32];
    __shared__ __align__(128) __nv_bfloat16 sB[3][128 * 32];

    const int tid  = threadIdx.x;
    const int wid  = tid >> 5, lane = tid & 31;
    const int wm   = (wid & 1) * 64;
    const int wn   = (wid >> 1) * 32;

    float acc[4][4][4];
#pragma unroll
    for (int i = 0; i < 4; ++i)
#pragma unroll
        for (int j = 0; j < 4; ++j)
#pragma unroll
            for (int q = 0; q < 4; ++q) acc[i][j][q] = 0.f;

    const int lrow = tid >> 2;          // 0..63 (+64 on second pass)
    const int lc   = tid & 3;

    const int NCH = 96;                 // 3 terms x 32 chunks of K=32
    auto chunk_offs = [] (int cidx, int& a_k, int& b_k) {
        int term = cidx >> 5, kk = cidx & 31;
        a_k = (term == 1 ? 1024 : 0) + kk * 32;
        b_k = (term == 2 ? 1024 : 0) + kk * 32;
    };
    auto load_stage = [&] (int cidx, int st) {
        int a_k, b_k; chunk_offs(cidx, a_k, b_k);
#pragma unroll
        for (int u = 0; u < 2; ++u) {
            int row = lrow + 64 * u;
            int pc  = lc ^ ((row >> 1) & 3);
            cp16(s2u(&sA[st][row * 32 + pc * 8]), A + (size_t)row * KB2 + a_k + lc * 8);
            cp16(s2u(&sB[st][row * 32 + pc * 8]), B + (size_t)row * KB2 + b_k + lc * 8);
        }
        cp_commit();
    };

    load_stage(0, 0);
    load_stage(1, 1);

    for (int c = 0; c < NCH; ++c) {
        const int buf = c % 3;
        if (c + 1 < NCH) cp_wait<1>(); else cp_wait<0>();
        __syncthreads();
        if (c + 2 < NCH) load_stage(c + 2, (c + 2) % 3);

#pragma unroll
        for (int ks = 0; ks < 2; ++ks) {
            uint32_t af[4][4];
#pragma unroll
            for (int im = 0; im < 4; ++im) {
                int row = wm + im * 16 + (lane & 15);
                int ch  = ks * 2 + ((lane >> 4) & 1);
                int pc  = ch ^ ((row >> 1) & 3);
                ldsm_x4(af[im], s2u(&sA[buf][row * 32 + pc * 8]));
            }
            uint32_t bfr[2][4];
#pragma unroll
            for (int ib = 0; ib < 2; ++ib) {
                int row = wn + ib * 16 + (lane & 7) + ((lane >> 4) & 1) * 8;
                int ch  = ks * 2 + ((lane >> 3) & 1);
                int pc  = ch ^ ((row >> 1) & 3);
                ldsm_x4(bfr[ib], s2u(&sB[buf][row * 32 + pc * 8]));
            }
#pragma unroll
            for (int im = 0; im < 4; ++im)
#pragma unroll
                for (int in = 0; in < 4; ++in)
                    mma16816(acc[im][in], af[im], &bfr[in >> 1][(in & 1) * 2]);
        }
    }

    const int group = lane >> 2, tg = lane & 3;
#pragma unroll
    for (int im = 0; im < 4; ++im) {
        int r0 = wm + im * 16 + group;
#pragma unroll
        for (int half = 0; half < 2; ++half) {
            float* crow = C + (size_t)(r0 + half * 8) * ldc;
#pragma unroll
            for (int in = 0; in < 4; ++in) {
                float2 v = make_float2(acc[im][in][half * 2]     * scale,
                                       acc[im][in][half * 2 + 1] * scale);
                *(float2*)(crow + wn + in * 8 + tg * 2) = v;
            }
        }
    }
}

__global__ __launch_bounds__(256, 2) void gemm_proj_tc()
{
    const int nt = blockIdx.x;
    const int m0 = blockIdx.y * 128;
    float* Cp; int ldc, n0; float scale = 1.f;
    if (nt < 4)       { Cp = g_q;  ldc = QKc; n0 = nt * 128;        scale = 0.125f; }
    else if (nt < 8)  { Cp = g_k;  ldc = QKc; n0 = (nt - 4)  * 128; }
    else if (nt < 16) { Cp = g_v;  ldc = Vc;  n0 = (nt - 8)  * 128; }
    else              { Cp = g_og; ldc = Vc;  n0 = (nt - 16) * 128; }
    mma_gemm_tile(g_xb + (size_t)m0 * KB2,
                  g_Wb + (size_t)nt * 128 * KB2,
                  Cp + (size_t)m0 * ldc + n0, ldc, scale);
}

__global__ __launch_bounds__(256, 2) void gemm_out_tc(float* __restrict__ y)
{
    const int n0 = blockIdx.x * 128;
    const int m0 = blockIdx.y * 128;
    mma_gemm_tile(g_houtb + (size_t)m0 * KB2,
                  g_Woutb + (size_t)n0 * KB2,
                  y + (size_t)m0 * Dc + n0, Dc, 1.f);
}

// ---------------- fused fp32 -> bf16 hi/lo split (all 6 tensors) -----------
__device__ __forceinline__ void split2(float v, __nv_bfloat16& h, __nv_bfloat16& l) {
    h = __float2bfloat16(v);
    l = __float2bfloat16(v - __bfloat162float(h));
}
// segment boundaries in float4 units
namespace {
constexpr int SEG0 =  524288;             // x     (2048 x 1024)
constexpr int SEG1 = SEG0 + 131072;       // Wq
constexpr int SEG2 = SEG1 + 131072;       // Wk
constexpr int SEG3 = SEG2 + 262144;       // Wv
constexpr int SEG4 = SEG3 + 262144;       // Wog
constexpr int SEG5 = SEG4 + 262144;       // Wout  -> total 1572864
}
__global__ void cvt_all(const float* __restrict__ x,
                        const float* __restrict__ Wq, const float* __restrict__ Wk,
                        const float* __restrict__ Wv, const float* __restrict__ Wog,
                        const float* __restrict__ Wout)
{
    int idx = blockIdx.x * 256 + threadIdx.x;
    const float* src; __nv_bfloat16* dst; int lidx;
    if      (idx < SEG0) { src = x;    dst = g_xb;              lidx = idx; }
    else if (idx < SEG1) { src = Wq;   dst = g_Wb;              lidx = idx - SEG0; }
    else if (idx < SEG2) { src = Wk;   dst = g_Wb +  512*KB2;   lidx = idx - SEG1; }
    else if (idx < SEG3) { src = Wv;   dst = g_Wb + 1024*KB2;   lidx = idx - SEG2; }
    else if (idx < SEG4) { src = Wog;  dst = g_Wb + 2048*KB2;   lidx = idx - SEG3; }
    else                 { src = Wout; dst = g_Woutb;           lidx = idx - SEG4; }
    int row = lidx >> 8;       // 256 float4 per 1024-wide row
    int c4  = lidx & 255;
    float4 v = ((const float4*)src)[lidx];
    __nv_bfloat16 h0,h1,h2,h3,l0,l1,l2,l3;
    split2(v.x,h0,l0); split2(v.y,h1,l1); split2(v.z,h2,l2); split2(v.w,h3,l3);
    __nv_bfloat162* dh = (__nv_bfloat162*)(dst + (size_t)row * KB2 + c4 * 4);
    dh[0] = __halves2bfloat162(h0, h1);
    dh[1] = __halves2bfloat162(h2, h3);
    __nv_bfloat162* dl = (__nv_bfloat162*)(dst + (size_t)row * KB2 + 1024 + c4 * 4);
    dl[0] = __halves2bfloat162(l0, l1);
    dl[1] = __halves2bfloat162(l2, l3);
}

// ---------------- gate GEMV: i_pre/f_pre = softcap(x @ W^T + b) ------------
__global__ void gates_kernel(const float* __restrict__ x,
                             const float* __restrict__ Wi, const float* __restrict__ bi,
                             const float* __restrict__ Wf, const float* __restrict__ bf)
{
    const int wid  = blockIdx.x * (blockDim.x >> 5) + (threadIdx.x >> 5);
    const int lane = threadIdx.x & 31;
    const int row  = wid >> 4;
    const int o    = wid & 15;
    const int h    = o & 7;
    const bool isF = (o >= 8);
    const float* Wp = isF ? Wf : Wi;
    const float* bp = isF ? bf : bi;
    const float4* xr = (const float4*)(x  + (size_t)row * Dc);
    const float4* wr = (const float4*)(Wp + (size_t)h   * Dc);
    float acc = 0.f;
#pragma unroll
    for (int c = lane; c < Dc/4; c += 32) {
        float4 xv = __ldg(&xr[c]);
        float4 wv = __ldg(&wr[c]);
        acc += xv.x*wv.x + xv.y*wv.y + xv.z*wv.z + xv.w*wv.w;
    }
#pragma unroll
    for (int off = 16; off > 0; off >>= 1)
        acc += __shfl_xor_sync(0xffffffffu, acc, off);
    if (lane == 0) {
        float pre = acc + bp[h];
        float cap = 15.f * tanhf(pre * (1.f/15.f));
        int b = row >> 10, t = row & (Sc - 1);
        int idx = (b * NHc + h) * Sc + t;
        if (isF) {
            float fl = (cap >= 0.f) ? -log1pf(expf(-cap))
                                    : (cap - log1pf(expf(cap)));
            g_flog[idx] = fl;
        } else {
            g_icap[idx] = cap;
        }
    }
}

// ---------------- max-state scan + activations (per (b,h)) -----------------
__global__ void scan_kernel()
{
    __shared__ float sFl[Sc], sIc[Sc], sM[Sc];
    const int bh  = blockIdx.x;
    const int tid = threadIdx.x;
    const float* fl = g_flog + bh * Sc;
    const float* ic = g_icap + bh * Sc;
    for (int t = tid; t < Sc; t += blockDim.x) { sFl[t] = fl[t]; sIc[t] = ic[t]; }
    __syncthreads();
    if (tid == 0) {
        float m = 0.f;
#pragma unroll 8
        for (int t = 0; t < Sc; ++t) {
            m = fmaxf(sFl[t] + m, sIc[t]);
            sM[t] = m;
        }
    }
    __syncthreads();
    for (int t = tid; t < Sc; t += blockDim.x) {
        float m  = sM[t];
        float mp = (t > 0) ? sM[t-1] : 0.f;
        int idx  = bh * Sc + t;
        g_fact[idx] = expf(sFl[t] + mp - m);
        g_iact[idx] = expf(sIc[t] - m);
        g_em[idx]   = expf(-m);
    }
}

// ---------------- n-scan + denominator: one channel per thread -------------
__global__ __launch_bounds__(64) void nscan_kernel()
{
    __shared__ float sP[32][65];
    const int bh = blockIdx.x;
    const int b = bh >> 3, h = bh & 7;
    const int d = threadIdx.x;
    const int warp = d >> 5, lane = d & 31;
    const float* kp = g_k + (size_t)b*Sc*QKc + h*DQKc + d;
    const float* qp = g_q + (size_t)b*Sc*QKc + h*DQKc + d;
    const float* fa = g_fact + bh*Sc;
    const float* ia = g_iact + bh*Sc;
    float n = 0.f;
    for (int tile = 0; tile < Sc/32; ++tile) {
        const int t0 = tile * 32;
#pragma unroll 8
        for (int s = 0; s < 32; ++s) {
            int t = t0 + s;
            float kv = __ldg(kp + (size_t)t * QKc);
            float qv = __ldg(qp + (size_t)t * QKc);
            n = fa[t]*n + ia[t]*kv;
            sP[s][d] = qv * n;
        }
        __syncthreads();
#pragma unroll
        for (int i = 0; i < 16; ++i) {
            int tt = warp * 16 + i;
            float v = sP[tt][lane] + sP[tt][lane + 32];
#pragma unroll
            for (int off = 16; off > 0; off >>= 1)
                v += __shfl_xor_sync(0xffffffffu, v, off);
            if (lane == 0) {
                int t = t0 + tt;
                float den = fmaxf(fabsf(v), g_em[bh*Sc + t]) + 1e-6f;
                g_invden[bh*Sc + t] = 1.f / den;
            }
        }
        __syncthreads();
    }
}

// ---------------- main C-state recurrence -----------------------------------
// grid (8 vblocks, 16 heads); block 256 = 16 v-cols x 16 d-slices (4 d each).
// 8 warps/block = 2 warps/SMSP for latency hiding.
__global__ __launch_bounds__(256) void recur_kernel()
{
    __shared__ float sK[32][64];
    __shared__ float sQ[32][64];
    __shared__ float sV[32][16];
    __shared__ float sS[3][32];
    const int vb = blockIdx.x;
    const int bh = blockIdx.y;
    const int b = bh >> 3, h = bh & 7;
    const int tid = threadIdx.x;
    const int vi = tid >> 4;               // 0..15 (v within block)
    const int dc = tid & 15;               // 0..15 (d slice of 4)

    float C[4];
#pragma unroll
    for (int j = 0; j < 4; ++j) C[j] = 0.f;

    float4 rk[2], rq[2], rv;
    float rs = 0.f;

    auto g_load = [&] (int t0) {
#pragma unroll
        for (int u = 0; u < 2; ++u) {
            int id = tid + 256*u;
            int r = id >> 4, c = id & 15;
            int gb = (b*Sc + t0 + r) * QKc + h * DQKc + c * 4;
            rk[u] = *(const float4*)&g_k[gb];
            rq[u] = *(const float4*)&g_q[gb];
        }
        if (tid < 128) {
            int r = tid >> 2, c = tid & 3;
            rv = *(const float4*)&g_v[(b*Sc + t0 + r) * Vc + h * DHVc + vb*16 + c*4];
        } else if (tid < 224) {
            int which = (tid - 128) >> 5, s = (tid - 128) & 31;
            const float* sp = (which == 0) ? g_fact : ((which == 1) ? g_iact : g_invden);
            rs = sp[bh*Sc + t0 + s];
        }
    };
    auto s_store = [&] () {
#pragma unroll
        for (int u = 0; u < 2; ++u) {
            int id = tid + 256*u;
            int r = id >> 4, c = id & 15;
            *(float4*)&sK[r][c*4] = rk[u];
            *(float4*)&sQ[r][c*4] = rq[u];
        }
        if (tid < 128) {
            int r = tid >> 2, c = tid & 3;
            *(float4*)&sV[r][c*4] = rv;
        } else if (tid < 224) {
            sS[(tid-128)>>5][(tid-128)&31] = rs;
        }
    };

    g_load(0);
    s_store();
    __syncthreads();

    const int NT = Sc / 32;
    for (int tile = 0; tile < NT; ++tile) {
        if (tile + 1 < NT) g_load((tile + 1) * 32);
#pragma unroll 4
        for (int s = 0; s < 32; ++s) {
            float fa  = sS[0][s];
            float iv  = sS[1][s] * sV[s][vi];
            float idn = sS[2][s];
            float4 k0 = *(const float4*)&sK[s][dc*4];
            float4 q0 = *(const float4*)&sQ[s][dc*4];
            C[0] = fa*C[0] + k0.x*iv;
            C[1] = fa*C[1] + k0.y*iv;
            C[2] = fa*C[2] + k0.z*iv;
            C[3] = fa*C[3] + k0.w*iv;
            float p = q0.x*C[0] + q0.y*C[1] + q0.z*C[2] + q0.w*C[3];
            p += __shfl_xor_sync(0xffffffffu, p, 1);
            p += __shfl_xor_sync(0xffffffffu, p, 2);
            p += __shfl_xor_sync(0xffffffffu, p, 4);
            p += __shfl_xor_sync(0xffffffffu, p, 8);
            if (dc == 0) {
                int t = tile*32 + s;
                g_h[(b*Sc + t) * Vc + h*DHVc + vb*16 + vi] = p * idn;
            }
        }
        if (tile + 1 < NT) {
            __syncthreads();
            s_store();
            __syncthreads();
        }
    }
}

// ------ per-head layernorm * gamma * sigmoid(o_pre) -> bf16 hi/lo pairs ----
__global__ void ln_gate_kernel(const float* __restrict__ gamma)
{
    const int row  = blockIdx.x;           // b*S + s
    const int hd   = threadIdx.x >> 5;
    const int lane = threadIdx.x & 31;
    const int base = row * Vc + hd * DHVc + lane * 4;
    float4 hv = *(const float4*)&g_h[base];
    float sm = hv.x + hv.y + hv.z + hv.w;
#pragma unroll
    for (int off = 16; off > 0; off >>= 1)
        sm += __shfl_xor_sync(0xffffffffu, sm, off);
    float mu = sm * (1.f/128.f);
    float dx = hv.x - mu, dy = hv.y - mu, dz = hv.z - mu, dw = hv.w - mu;
    float sq = dx*dx + dy*dy + dz*dz + dw*dw;
#pragma unroll
    for (int off = 16; off > 0; off >>= 1)
        sq += __shfl_xor_sync(0xffffffffu, sq, off);
    float rstd = rsqrtf(sq * (1.f/128.f) + 1e-6f);
    float4 gm = *(const float4*)&gamma[hd * DHVc + lane * 4];
    float4 og = *(const float4*)&g_og[base];
    float ox = dx * rstd * gm.x / (1.f + expf(-og.x));
    float oy = dy * rstd * gm.y / (1.f + expf(-og.y));
    float oz = dz * rstd * gm.z / (1.f + expf(-og.z));
    float ow = dw * rstd * gm.w / (1.f + expf(-og.w));
    __nv_bfloat16 h0,h1,h2,h3,l0,l1,l2,l3;
    split2(ox,h0,l0); split2(oy,h1,l1); split2(oz,h2,l2); split2(ow,h3,l3);
    const int col = hd * DHVc + lane * 4;
    __nv_bfloat162* dh = (__nv_bfloat162*)(g_houtb + (size_t)row * KB2 + col);
    dh[0] = __halves2bfloat162(h0, h1);
    dh[1] = __halves2bfloat162(h2, h3);
    __nv_bfloat162* dl = (__nv_bfloat162*)(g_houtb + (size_t)row * KB2 + 1024 + col);
    dl[0] = __halves2bfloat162(l0, l1);
    dl[1] = __halves2bfloat162(l2, l3);
}

// ---------------- launch ----------------------------------------------------
extern "C" void kernel_launch(void* const* d_in, const int* in_sizes, int n_in,
                              void* d_out, int out_size)
{
    const float* x     = (const float*)d_in[0];
    const float* Wq    = (const float*)d_in[1];
    const float* Wk    = (const float*)d_in[2];
    const float* Wv    = (const float*)d_in[3];
    const float* Wog   = (const float*)d_in[4];
    const float* Wi    = (const float*)d_in[5];
    const float* bi    = (const float*)d_in[6];
    const float* Wf    = (const float*)d_in[7];
    const float* bf    = (const float*)d_in[8];
    const float* gamma = (const float*)d_in[9];
    const float* Wout  = (const float*)d_in[10];
    float* y = (float*)d_out;

    // fused fp32 -> bf16 hi/lo splits (1572864 float4 / 256)
    cvt_all<<<6144, 256>>>(x, Wq, Wk, Wv, Wog, Wout);
    // q,k,v,og projections on tensor cores (mma.sync, 3-term bf16 split)
    gemm_proj_tc<<<dim3(24, 16), 256>>>();
    // i/f gate pre-activations (fp32 exact)
    gates_kernel<<<4096, 256>>>(x, Wi, bi, Wf, bf);
    // max-state scan
    scan_kernel<<<16, 128>>>();
    // n recurrence + denominators (channel-parallel)
    nscan_kernel<<<16, 64>>>();
    // main C recurrence -> h
    recur_kernel<<<dim3(8, 16), 256>>>();
    // layernorm * gamma * sigmoid(og) -> bf16 split
    ln_gate_kernel<<<Bc * Sc, 256>>>(gamma);
    // y = h_out @ Wout^T on tensor cores
    gemm_out_tc<<<dim3(8, 16), 256>>>(y);
}

// round 8
// speedup vs baseline: 1.6119x; 1.0358x over previous
#include <cuda_runtime.h>
#include <cuda_bf16.h>
#include <math.h>
#include <stdint.h>

// ---------------- problem constants ----------------
namespace {
constexpr int Bc   = 2;
constexpr int Sc   = 1024;
constexpr int Dc   = 1024;
constexpr int NHc  = 8;
constexpr int QKc  = 512;
constexpr int Vc   = 1024;
constexpr int DQKc = 64;
constexpr int DHVc = 128;
constexpr int KB2  = 2048;   // bf16 hi|lo split row width
}

// ---------------- scratch (device globals) ---------------------------------
__device__ float g_q     [Bc*Sc*QKc];   // pre-scaled q
__device__ float g_k     [Bc*Sc*QKc];
__device__ float g_v     [Bc*Sc*Vc];
__device__ float g_og    [Bc*Sc*Vc];
__device__ float g_h     [Bc*Sc*Vc];
__device__ float g_icap  [Bc*NHc*Sc];
__device__ float g_flog  [Bc*NHc*Sc];
__device__ float g_fact  [Bc*NHc*Sc];
__device__ float g_iact  [Bc*NHc*Sc];
__device__ float g_em    [Bc*NHc*Sc];
__device__ float g_invden[Bc*NHc*Sc];

__device__ __nv_bfloat16 g_xb   [Bc*Sc*KB2];
__device__ __nv_bfloat16 g_Wb   [3072*KB2];       // [Wq;Wk;Wv;Wog]
__device__ __nv_bfloat16 g_Woutb[Dc*KB2];
__device__ __nv_bfloat16 g_houtb[Bc*Sc*KB2];

// ---------------- mma.sync helpers -----------------------------------------
__device__ __forceinline__ uint32_t s2u(const void* p) {
    return (uint32_t)__cvta_generic_to_shared(p);
}
__device__ __forceinline__ void cp16(uint32_t saddr, const void* g) {
    asm volatile("cp.async.cg.shared.global [%0], [%1], 16;"
                 :: "r"(saddr), "l"(g) : "memory");
}
__device__ __forceinline__ void cp_commit() {
    asm volatile("cp.async.commit_group;" ::: "memory");
}
template <int N>
__device__ __forceinline__ void cp_wait() {
    asm volatile("cp.async.wait_group %0;" :: "n"(N) : "memory");
}
__device__ __forceinline__ void ldsm_x4(uint32_t* r, uint32_t addr) {
    asm volatile("ldmatrix.sync.aligned.m8n8.x4.shared.b16 {%0,%1,%2,%3}, [%4];"
                 : "=r"(r[0]), "=r"(r[1]), "=r"(r[2]), "=r"(r[3]) : "r"(addr));
}
__device__ __forceinline__ void mma16816(float* d, const uint32_t* a, const uint32_t* b) {
    asm volatile(
        "mma.sync.aligned.m16n8k16.row.col.f32.bf16.bf16.f32 "
        "{%0,%1,%2,%3}, {%4,%5,%6,%7}, {%8,%9}, {%0,%1,%2,%3};"
        : "+f"(d[0]), "+f"(d[1]), "+f"(d[2]), "+f"(d[3])
        : "r"(a[0]), "r"(a[1]), "r"(a[2]), "r"(a[3]), "r"(b[0]), "r"(b[1]));
}

// ---------------- 128x128 bf16 mma.sync GEMM tile, 3-term split K ----------
__device__ __forceinline__ void mma_gemm_tile(
    const __nv_bfloat16* __restrict__ A,
    const __nv_bfloat16* __restrict__ B,
    float* __restrict__ C, int ldc, float scale)
{
    __shared__ __align__(128) __nv_bfloat16 sA[3][128 * 32];
    __shared__ __align__(128) __nv_bfloat16 sB[3][128 * 32];

    const int tid  = threadIdx.x;
    const int wid  = tid >> 5, lane = tid & 31;
    const int wm   = (wid & 1) * 64;
    const int wn   = (wid >> 1) * 32;

    float acc[4][4][4];
#pragma unroll
    for (int i = 0; i < 4; ++i)
#pragma unroll
        for (int j = 0; j < 4; ++j)
#pragma unroll
            for (int q = 0; q < 4; ++q) acc[i][j][q] = 0.f;

    const int lrow = tid >> 2;
    const int lc   = tid & 3;

    const int NCH = 96;
    auto chunk_offs = [] (int cidx, int& a_k, int& b_k) {
        int term = cidx >> 5, kk = cidx & 31;
        a_k = (term == 1 ? 1024 : 0) + kk * 32;
        b_k = (term == 2 ? 1024 : 0) + kk * 32;
    };
    auto load_stage = [&] (int cidx, int st) {
        int a_k, b_k; chunk_offs(cidx, a_k, b_k);
#pragma unroll
        for (int u = 0; u < 2; ++u) {
            int row = lrow + 64 * u;
            int pc  = lc ^ ((row >> 1) & 3);
            cp16(s2u(&sA[st][row * 32 + pc * 8]), A + (size_t)row * KB2 + a_k + lc * 8);
            cp16(s2u(&sB[st][row * 32 + pc * 8]), B + (size_t)row * KB2 + b_k + lc * 8);
        }
        cp_commit();
    };

    load_stage(0, 0);
    load_stage(1, 1);

    for (int c = 0; c < NCH; ++c) {
        const int buf = c % 3;
        if (c + 1 < NCH) cp_wait<1>(); else cp_wait<0>();
        __syncthreads();
        if (c + 2 < NCH) load_stage(c + 2, (c + 2) % 3);

#pragma unroll
        for (int ks = 0; ks < 2; ++ks) {
            uint32_t af[4][4];
#pragma unroll
            for (int im = 0; im < 4; ++im) {
                int row = wm + im * 16 + (lane & 15);
                int ch  = ks * 2 + ((lane >> 4) & 1);
                int pc  = ch ^ ((row >> 1) & 3);
                ldsm_x4(af[im], s2u(&sA[buf][row * 32 + pc * 8]));
            }
            uint32_t bfr[2][4];
#pragma unroll
            for (int ib = 0; ib < 2; ++ib) {
                int row = wn + ib * 16 + (lane & 7) + ((lane >> 4) & 1) * 8;
                int ch  = ks * 2 + ((lane >> 3) & 1);
                int pc  = ch ^ ((row >> 1) & 3);
                ldsm_x4(bfr[ib], s2u(&sB[buf][row * 32 + pc * 8]));
            }
#pragma unroll
            for (int im = 0; im < 4; ++im)
#pragma unroll
                for (int in = 0; in < 4; ++in)
                    mma16816(acc[im][in], af[im], &bfr[in >> 1][(in & 1) * 2]);
        }
    }

    const int group = lane >> 2, tg = lane & 3;
#pragma unroll
    for (int im = 0; im < 4; ++im) {
        int r0 = wm + im * 16 + group;
#pragma unroll
        for (int half = 0; half < 2; ++half) {
            float* crow = C + (size_t)(r0 + half * 8) * ldc;
#pragma unroll
            for (int in = 0; in < 4; ++in) {
                float2 v = make_float2(acc[im][in][half * 2]     * scale,
                                       acc[im][in][half * 2 + 1] * scale);
                *(float2*)(crow + wn + in * 8 + tg * 2) = v;
            }
        }
    }
}

__global__ __launch_bounds__(256, 2) void gemm_proj_tc()
{
    const int nt = blockIdx.x;
    const int m0 = blockIdx.y * 128;
    float* Cp; int ldc, n0; float scale = 1.f;
    if (nt < 4)       { Cp = g_q;  ldc = QKc; n0 = nt * 128;        scale = 0.125f; }
    else if (nt < 8)  { Cp = g_k;  ldc = QKc; n0 = (nt - 4)  * 128; }
    else if (nt < 16) { Cp = g_v;  ldc = Vc;  n0 = (nt - 8)  * 128; }
    else              { Cp = g_og; ldc = Vc;  n0 = (nt - 16) * 128; }
    mma_gemm_tile(g_xb + (size_t)m0 * KB2,
                  g_Wb + (size_t)nt * 128 * KB2,
                  Cp + (size_t)m0 * ldc + n0, ldc, scale);
}

__global__ __launch_bounds__(256, 2) void gemm_out_tc(float* __restrict__ y)
{
    const int n0 = blockIdx.x * 128;
    const int m0 = blockIdx.y * 128;
    mma_gemm_tile(g_houtb + (size_t)m0 * KB2,
                  g_Woutb + (size_t)n0 * KB2,
                  y + (size_t)m0 * Dc + n0, Dc, 1.f);
}

// ---------------- fused fp32 -> bf16 hi/lo split ----------------------------
__device__ __forceinline__ void split2(float v, __nv_bfloat16& h, __nv_bfloat16& l) {
    h = __float2bfloat16(v);
    l = __float2bfloat16(v - __bfloat162float(h));
}
namespace {
constexpr int SEG0 =  524288;             // x     (float4 units)
constexpr int SEG1 = SEG0 + 131072;       // Wq
constexpr int SEG2 = SEG1 + 131072;       // Wk
constexpr int SEG3 = SEG2 + 262144;       // Wv
constexpr int SEG4 = SEG3 + 262144;       // Wog
constexpr int SEG5 = SEG4 + 262144;       // Wout -> total 1572864
}
// 2 consecutive float4 per thread; 16B packed hi / lo stores
__global__ void cvt_all2(const float* __restrict__ x,
                         const float* __restrict__ Wq, const float* __restrict__ Wk,
                         const float* __restrict__ Wv, const float* __restrict__ Wog,
                         const float* __restrict__ Wout)
{
    int idx = (blockIdx.x * 256 + threadIdx.x) * 2;
    const float* src; __nv_bfloat16* dst; int lidx;
    if      (idx < SEG0) { src = x;    dst = g_xb;              lidx = idx; }
    else if (idx < SEG1) { src = Wq;   dst = g_Wb;              lidx = idx - SEG0; }
    else if (idx < SEG2) { src = Wk;   dst = g_Wb +  512*KB2;   lidx = idx - SEG1; }
    else if (idx < SEG3) { src = Wv;   dst = g_Wb + 1024*KB2;   lidx = idx - SEG2; }
    else if (idx < SEG4) { src = Wog;  dst = g_Wb + 2048*KB2;   lidx = idx - SEG3; }
    else                 { src = Wout; dst = g_Woutb;           lidx = idx - SEG4; }
    int row = lidx >> 8;
    int c4  = lidx & 255;
    float4 v0 = ((const float4*)src)[lidx];
    float4 v1 = ((const float4*)src)[lidx + 1];
    float vf[8] = {v0.x, v0.y, v0.z, v0.w, v1.x, v1.y, v1.z, v1.w};
    uint32_t ph[4], pl[4];
#pragma unroll
    for (int p = 0; p < 4; ++p) {
        __nv_bfloat16 h0, l0, h1, l1;
        split2(vf[2*p],   h0, l0);
        split2(vf[2*p+1], h1, l1);
        __nv_bfloat162 hh = __halves2bfloat162(h0, h1);
        __nv_bfloat162 ll = __halves2bfloat162(l0, l1);
        ph[p] = *reinterpret_cast<uint32_t*>(&hh);
        pl[p] = *reinterpret_cast<uint32_t*>(&ll);
    }
    *(uint4*)(dst + (size_t)row * KB2 + c4 * 4)        = make_uint4(ph[0], ph[1], ph[2], ph[3]);
    *(uint4*)(dst + (size_t)row * KB2 + 1024 + c4 * 4) = make_uint4(pl[0], pl[1], pl[2], pl[3]);
}

// ---------------- gate GEMV: 4 outputs per warp -----------------------------
__global__ void gates_kernel(const float* __restrict__ x,
                             const float* __restrict__ Wi, const float* __restrict__ bi,
                             const float* __restrict__ Wf, const float* __restrict__ bf)
{
    const int wid  = blockIdx.x * 8 + (threadIdx.x >> 5);  // 0..8191
    const int lane = threadIdx.x & 31;
    const int row  = wid >> 2;          // 0..2047
    const int g    = wid & 3;           // output group: o = g*4 + j
    const float4* xr = (const float4*)(x + (size_t)row * Dc);
    const float4* wr[4];
#pragma unroll
    for (int j = 0; j < 4; ++j) {
        int o = g * 4 + j;
        const float* Wp = (o < 8) ? Wi : Wf;
        wr[j] = (const float4*)(Wp + (size_t)(o & 7) * Dc);
    }
    float acc[4] = {0.f, 0.f, 0.f, 0.f};
#pragma unroll 4
    for (int c = lane; c < Dc/4; c += 32) {
        float4 xv = __ldg(&xr[c]);
#pragma unroll
        for (int j = 0; j < 4; ++j) {
            float4 wv = __ldg(&wr[j][c]);
            acc[j] += xv.x*wv.x + xv.y*wv.y + xv.z*wv.z + xv.w*wv.w;
        }
    }
#pragma unroll
    for (int j = 0; j < 4; ++j)
#pragma unroll
        for (int off = 16; off > 0; off >>= 1)
            acc[j] += __shfl_xor_sync(0xffffffffu, acc[j], off);
    if (lane == 0) {
        int b = row >> 10, t = row & (Sc - 1);
#pragma unroll
        for (int j = 0; j < 4; ++j) {
            int o = g * 4 + j;
            int h = o & 7;
            float pre = acc[j] + ((o < 8) ? bi[h] : bf[h]);
            float cap = 15.f * tanhf(pre * (1.f/15.f));
            int idx = (b * NHc + h) * Sc + t;
            if (o >= 8) {
                float fl = (cap >= 0.f) ? -log1pf(expf(-cap))
                                        : (cap - log1pf(expf(cap)));
                g_flog[idx] = fl;
            } else {
                g_icap[idx] = cap;
            }
        }
    }
}

// ---------------- parallel max-plus scan (per (b,h)) ------------------------
__global__ __launch_bounds__(128) void scan_kernel()
{
    __shared__ float wA[4], wB[4];
    const int bh = blockIdx.x, tid = threadIdx.x;
    const int lane = tid & 31, w = tid >> 5;
    const float* fl = g_flog + bh * Sc + tid * 8;
    const float* ic = g_icap + bh * Sc + tid * 8;
    float a[8], b[8];
#pragma unroll
    for (int j = 0; j < 8; ++j) { a[j] = fl[j]; b[j] = ic[j]; }
    // segment transform (A,B): m -> max(m + A, B)
    float A = 0.f, B = -1e30f;
#pragma unroll
    for (int j = 0; j < 8; ++j) { B = fmaxf(B + a[j], b[j]); A += a[j]; }
    // warp inclusive scan: compose(prev, cur) = (Ap+Ac, max(Bp+Ac, Bc))
#pragma unroll
    for (int off = 1; off < 32; off <<= 1) {
        float A2 = __shfl_up_sync(0xffffffffu, A, off);
        float B2 = __shfl_up_sync(0xffffffffu, B, off);
        if (lane >= off) { B = fmaxf(B2 + A, B); A = A2 + A; }
    }
    if (lane == 31) { wA[w] = A; wB[w] = B; }
    __syncthreads();
    float pA = 0.f, pB = -1e30f;
    for (int ww = 0; ww < w; ++ww) { pB = fmaxf(pB + wA[ww], wB[ww]); pA += wA[ww]; }
    // exclusive within warp
    float eA = __shfl_up_sync(0xffffffffu, A, 1);
    float eB = __shfl_up_sync(0xffffffffu, B, 1);
    if (lane == 0) { eA = 0.f; eB = -1e30f; }
    float EB = fmaxf(pB + eA, eB);
    float EA = pA + eA;
    float m = fmaxf(EA, EB);          // prefix applied to m0 = 0
    const int base = bh * Sc + tid * 8;
#pragma unroll
    for (int j = 0; j < 8; ++j) {
        float mp = m;
        m = fmaxf(a[j] + mp, b[j]);
        g_fact[base + j] = expf(a[j] + mp - m);
        g_iact[base + j] = expf(b[j] - m);
        g_em  [base + j] = expf(-m);
    }
}

// ---------------- n-scan + denominator: one channel per thread -------------
__global__ __launch_bounds__(64) void nscan_kernel()
{
    __shared__ float sP[32][65];
    const int bh = blockIdx.x;
    const int b = bh >> 3, h = bh & 7;
    const int d = threadIdx.x;
    const int warp = d >> 5, lane = d & 31;
    const float* kp = g_k + (size_t)b*Sc*QKc + h*DQKc + d;
    const float* qp = g_q + (size_t)b*Sc*QKc + h*DQKc + d;
    const float* fa = g_fact + bh*Sc;
    const float* ia = g_iact + bh*Sc;
    float n = 0.f;
    for (int tile = 0; tile < Sc/32; ++tile) {
        const int t0 = tile * 32;
#pragma unroll 8
        for (int s = 0; s < 32; ++s) {
            int t = t0 + s;
            float kv = __ldg(kp + (size_t)t * QKc);
            float qv = __ldg(qp + (size_t)t * QKc);
            n = fa[t]*n + ia[t]*kv;
            sP[s][d] = qv * n;
        }
        __syncthreads();
#pragma unroll
        for (int i = 0; i < 16; ++i) {
            int tt = warp * 16 + i;
            float v = sP[tt][lane] + sP[tt][lane + 32];
#pragma unroll
            for (int off = 16; off > 0; off >>= 1)
                v += __shfl_xor_sync(0xffffffffu, v, off);
            if (lane == 0) {
                int t = t0 + tt;
                float den = fmaxf(fabsf(v), g_em[bh*Sc + t]) + 1e-6f;
                g_invden[bh*Sc + t] = 1.f / den;
            }
        }
        __syncthreads();
    }
}

// ---------------- main C-state recurrence -----------------------------------
__global__ __launch_bounds__(256) void recur_kernel()
{
    __shared__ float sK[32][64];
    __shared__ float sQ[32][64];
    __shared__ float sV[32][16];
    __shared__ float sS[3][32];
    const int vb = blockIdx.x;
    const int bh = blockIdx.y;
    const int b = bh >> 3, h = bh & 7;
    const int tid = threadIdx.x;
    const int vi = tid >> 4;
    const int dc = tid & 15;

    float C[4] = {0.f, 0.f, 0.f, 0.f};
    float4 rk[2], rq[2], rv;
    float rs = 0.f;

    auto g_load = [&] (int t0) {
#pragma unroll
        for (int u = 0; u < 2; ++u) {
            int id = tid + 256*u;
            int r = id >> 4, c = id & 15;
            int gb = (b*Sc + t0 + r) * QKc + h * DQKc + c * 4;
            rk[u] = *(const float4*)&g_k[gb];
            rq[u] = *(const float4*)&g_q[gb];
        }
        if (tid < 128) {
            int r = tid >> 2, c = tid & 3;
            rv = *(const float4*)&g_v[(b*Sc + t0 + r) * Vc + h * DHVc + vb*16 + c*4];
        } else if (tid < 224) {
            int which = (tid - 128) >> 5, s = (tid - 128) & 31;
            const float* sp = (which == 0) ? g_fact : ((which == 1) ? g_iact : g_invden);
            rs = sp[bh*Sc + t0 + s];
        }
    };
    auto s_store = [&] () {
#pragma unroll
        for (int u = 0; u < 2; ++u) {
            int id = tid + 256*u;
            int r = id >> 4, c = id & 15;
            *(float4*)&sK[r][c*4] = rk[u];
            *(float4*)&sQ[r][c*4] = rq[u];
        }
        if (tid < 128) {
            int r = tid >> 2, c = tid & 3;
            *(float4*)&sV[r][c*4] = rv;
        } else if (tid < 224) {
            sS[(tid-128)>>5][(tid-128)&31] = rs;
        }
    };

    g_load(0);
    s_store();
    __syncthreads();

    const int NT = Sc / 32;
    for (int tile = 0; tile < NT; ++tile) {
        if (tile + 1 < NT) g_load((tile + 1) * 32);
#pragma unroll 4
        for (int s = 0; s < 32; ++s) {
            float fa  = sS[0][s];
            float iv  = sS[1][s] * sV[s][vi];
            float idn = sS[2][s];
            float4 k0 = *(const float4*)&sK[s][dc*4];
            float4 q0 = *(const float4*)&sQ[s][dc*4];
            C[0] = fa*C[0] + k0.x*iv;
            C[1] = fa*C[1] + k0.y*iv;
            C[2] = fa*C[2] + k0.z*iv;
            C[3] = fa*C[3] + k0.w*iv;
            float p = q0.x*C[0] + q0.y*C[1] + q0.z*C[2] + q0.w*C[3];
            p += __shfl_xor_sync(0xffffffffu, p, 1);
            p += __shfl_xor_sync(0xffffffffu, p, 2);
            p += __shfl_xor_sync(0xffffffffu, p, 4);
            p += __shfl_xor_sync(0xffffffffu, p, 8);
            if (dc == 0) {
                int t = tile*32 + s;
                g_h[(b*Sc + t) * Vc + h*DHVc + vb*16 + vi] = p * idn;
            }
        }
        if (tile + 1 < NT) {
            __syncthreads();
            s_store();
            __syncthreads();
        }
    }
}

// ------ per-head layernorm * gamma * sigmoid(o_pre) -> bf16 hi/lo pairs ----
__global__ void ln_gate_kernel(const float* __restrict__ gamma)
{
    const int row  = blockIdx.x;
    const int hd   = threadIdx.x >> 5;
    const int lane = threadIdx.x & 31;
    const int base = row * Vc + hd * DHVc + lane * 4;
    float4 hv = *(const float4*)&g_h[base];
    float sm = hv.x + hv.y + hv.z + hv.w;
#pragma unroll
    for (int off = 16; off > 0; off >>= 1)
        sm += __shfl_xor_sync(0xffffffffu, sm, off);
    float mu = sm * (1.f/128.f);
    float dx = hv.x - mu, dy = hv.y - mu, dz = hv.z - mu, dw = hv.w - mu;
    float sq = dx*dx + dy*dy + dz*dz + dw*dw;
#pragma unroll
    for (int off = 16; off > 0; off >>= 1)
        sq += __shfl_xor_sync(0xffffffffu, sq, off);
    float rstd = rsqrtf(sq * (1.f/128.f) + 1e-6f);
    float4 gm = *(const float4*)&gamma[hd * DHVc + lane * 4];
    float4 og = *(const float4*)&g_og[base];
    float ox = dx * rstd * gm.x / (1.f + expf(-og.x));
    float oy = dy * rstd * gm.y / (1.f + expf(-og.y));
    float oz = dz * rstd * gm.z / (1.f + expf(-og.z));
    float ow = dw * rstd * gm.w / (1.f + expf(-og.w));
    __nv_bfloat16 h0,h1,h2,h3,l0,l1,l2,l3;
    split2(ox,h0,l0); split2(oy,h1,l1); split2(oz,h2,l2); split2(ow,h3,l3);
    const int col = hd * DHVc + lane * 4;
    __nv_bfloat162* dh = (__nv_bfloat162*)(g_houtb + (size_t)row * KB2 + col);
    dh[0] = __halves2bfloat162(h0, h1);
    dh[1] = __halves2bfloat162(h2, h3);
    __nv_bfloat162* dl = (__nv_bfloat162*)(g_houtb + (size_t)row * KB2 + 1024 + col);
    dl[0] = __halves2bfloat162(l0, l1);
    dl[1] = __halves2bfloat162(l2, l3);
}

// ---------------- launch ----------------------------------------------------
extern "C" void kernel_launch(void* const* d_in, const int* in_sizes, int n_in,
                              void* d_out, int out_size)
{
    const float* x     = (const float*)d_in[0];
    const float* Wq    = (const float*)d_in[1];
    const float* Wk    = (const float*)d_in[2];
    const float* Wv    = (const float*)d_in[3];
    const float* Wog   = (const float*)d_in[4];
    const float* Wi    = (const float*)d_in[5];
    const float* bi    = (const float*)d_in[6];
    const float* Wf    = (const float*)d_in[7];
    const float* bf    = (const float*)d_in[8];
    const float* gamma = (const float*)d_in[9];
    const float* Wout  = (const float*)d_in[10];
    float* y = (float*)d_out;

    // fork a side stream for gates+scan (depend only on raw x)
    cudaStream_t s2;
    cudaStreamCreateWithFlags(&s2, cudaStreamNonBlocking);
    cudaEvent_t e1, e2;
    cudaEventCreateWithFlags(&e1, cudaEventDisableTiming);
    cudaEventCreateWithFlags(&e2, cudaEventDisableTiming);

    cudaEventRecord(e1, 0);
    cudaStreamWaitEvent(s2, e1, 0);
    gates_kernel<<<1024, 256, 0, s2>>>(x, Wi, bi, Wf, bf);
    scan_kernel<<<16, 128, 0, s2>>>();
    cudaEventRecord(e2, s2);

    // main stream: conversions + projections
    cvt_all2<<<3072, 256>>>(x, Wq, Wk, Wv, Wog, Wout);
    gemm_proj_tc<<<dim3(24, 16), 256>>>();

    // join: nscan needs q,k (proj) + fact/iact/em (scan)
    cudaStreamWaitEvent(0, e2, 0);
    nscan_kernel<<<16, 64>>>();
    recur_kernel<<<dim3(8, 16), 256>>>();
    ln_gate_kernel<<<Bc * Sc, 256>>>(gamma);
    gemm_out_tc<<<dim3(8, 16), 256>>>(y);

    cudaEventDestroy(e1);
    cudaEventDestroy(e2);
    cudaStreamDestroy(s2);
}

// round 11
// speedup vs baseline: 1.6651x; 1.0330x over previous
#include <cuda_runtime.h>
#include <cuda_bf16.h>
#include <math.h>
#include <stdint.h>

// ---------------- problem constants ----------------
namespace {
constexpr int Bc   = 2;
constexpr int Sc   = 1024;
constexpr int Dc   = 1024;
constexpr int NHc  = 8;
constexpr int QKc  = 512;
constexpr int Vc   = 1024;
constexpr int DQKc = 64;
constexpr int DHVc = 128;
constexpr int KB2  = 2048;   // bf16 hi|lo split row width
}

// ---------------- scratch (device globals) ---------------------------------
__device__ float g_q     [Bc*Sc*QKc];   // pre-scaled q
__device__ float g_k     [Bc*Sc*QKc];
__device__ float g_v     [Bc*Sc*Vc];
__device__ float g_og    [Bc*Sc*Vc];
__device__ float g_h     [Bc*Sc*Vc];
__device__ float g_icap  [Bc*NHc*Sc];
__device__ float g_flog  [Bc*NHc*Sc];
__device__ float g_fact  [Bc*NHc*Sc];
__device__ float g_iact  [Bc*NHc*Sc];
__device__ float g_em    [Bc*NHc*Sc];
__device__ float g_invden[Bc*NHc*Sc];

__device__ __nv_bfloat16 g_xb   [Bc*Sc*KB2];
__device__ __nv_bfloat16 g_Wb   [3072*KB2];       // [Wq;Wk;Wv;Wog]
__device__ __nv_bfloat16 g_Woutb[Dc*KB2];
__device__ __nv_bfloat16 g_houtb[Bc*Sc*KB2];

// ---------------- mma.sync helpers -----------------------------------------
__device__ __forceinline__ uint32_t s2u(const void* p) {
    return (uint32_t)__cvta_generic_to_shared(p);
}
__device__ __forceinline__ void cp16(uint32_t saddr, const void* g) {
    asm volatile("cp.async.cg.shared.global [%0], [%1], 16;"
                 :: "r"(saddr), "l"(g) : "memory");
}
__device__ __forceinline__ void cp_commit() {
    asm volatile("cp.async.commit_group;" ::: "memory");
}
template <int N>
__device__ __forceinline__ void cp_wait() {
    asm volatile("cp.async.wait_group %0;" :: "n"(N) : "memory");
}
__device__ __forceinline__ void ldsm_x4(uint32_t* r, uint32_t addr) {
    asm volatile("ldmatrix.sync.aligned.m8n8.x4.shared.b16 {%0,%1,%2,%3}, [%4];"
                 : "=r"(r[0]), "=r"(r[1]), "=r"(r[2]), "=r"(r[3]) : "r"(addr));
}
__device__ __forceinline__ void mma16816(float* d, const uint32_t* a, const uint32_t* b) {
    asm volatile(
        "mma.sync.aligned.m16n8k16.row.col.f32.bf16.bf16.f32 "
        "{%0,%1,%2,%3}, {%4,%5,%6,%7}, {%8,%9}, {%0,%1,%2,%3};"
        : "+f"(d[0]), "+f"(d[1]), "+f"(d[2]), "+f"(d[3])
        : "r"(a[0]), "r"(a[1]), "r"(a[2]), "r"(a[3]), "r"(b[0]), "r"(b[1]));
}

// ---------------- 128x128 bf16 mma.sync GEMM tile, 3-term split K ----------
// 128 threads = 4 warps (2m x 2n), warp tile 64x64, BK=32, 3-stage pipeline.
// D = Ah@Bh^T + Al@Bh^T + Ah@Bl^T (fp32 accumulate).
__device__ __forceinline__ void mma_gemm_tile(
    const __nv_bfloat16* __restrict__ A,
    const __nv_bfloat16* __restrict__ B,
    float* __restrict__ C, int ldc, float scale)
{
    __shared__ __align__(128) __nv_bfloat16 sA[3][128 * 32];
    __shared__ __align__(128) __nv_bfloat16 sB[3][128 * 32];

    const int tid  = threadIdx.x;
    const int wid  = tid >> 5, lane = tid & 31;
    const int wm   = (wid & 1) * 64;
    const int wn   = (wid >> 1) * 64;

    float acc[4][8][4];
#pragma unroll
    for (int i = 0; i < 4; ++i)
#pragma unroll
        for (int j = 0; j < 8; ++j)
#pragma unroll
            for (int q = 0; q < 4; ++q) acc[i][j][q] = 0.f;

    const int lrow = tid >> 2;          // 0..31
    const int lc   = tid & 3;

    const int NCH = 96;                 // 3 terms x 32 chunks of K=32
    auto load_stage = [&] (int cidx, int st) {
        int term = cidx >> 5, kk = cidx & 31;
        int a_k = (term == 1 ? 1024 : 0) + kk * 32;
        int b_k = (term == 2 ? 1024 : 0) + kk * 32;
#pragma unroll
        for (int u = 0; u < 4; ++u) {
            int row = lrow + 32 * u;
            int pc  = lc ^ ((row >> 1) & 3);
            cp16(s2u(&sA[st][row * 32 + pc * 8]), A + (size_t)row * KB2 + a_k + lc * 8);
            cp16(s2u(&sB[st][row * 32 + pc * 8]), B + (size_t)row * KB2 + b_k + lc * 8);
        }
        cp_commit();
    };

    load_stage(0, 0);
    load_stage(1, 1);

    for (int c = 0; c < NCH; ++c) {
        const int buf = c % 3;
        if (c + 1 < NCH) cp_wait<1>(); else cp_wait<0>();
        __syncthreads();
        if (c + 2 < NCH) load_stage(c + 2, (c + 2) % 3);

#pragma unroll
        for (int ks = 0; ks < 2; ++ks) {
            uint32_t af[4][4];
#pragma unroll
            for (int im = 0; im < 4; ++im) {
                int row = wm + im * 16 + (lane & 15);
                int ch  = ks * 2 + ((lane >> 4) & 1);
                int pc  = ch ^ ((row >> 1) & 3);
                ldsm_x4(af[im], s2u(&sA[buf][row * 32 + pc * 8]));
            }
            uint32_t bfr[4][4];
#pragma unroll
            for (int ib = 0; ib < 4; ++ib) {
                int row = wn + ib * 16 + (lane & 7) + ((lane >> 4) & 1) * 8;
                int ch  = ks * 2 + ((lane >> 3) & 1);
                int pc  = ch ^ ((row >> 1) & 3);
                ldsm_x4(bfr[ib], s2u(&sB[buf][row * 32 + pc * 8]));
            }
#pragma unroll
            for (int im = 0; im < 4; ++im)
#pragma unroll
                for (int in = 0; in < 8; ++in)
                    mma16816(acc[im][in], af[im], &bfr[in >> 1][(in & 1) * 2]);
        }
    }

    const int group = lane >> 2, tg = lane & 3;
#pragma unroll
    for (int im = 0; im < 4; ++im) {
        int r0 = wm + im * 16 + group;
#pragma unroll
        for (int half = 0; half < 2; ++half) {
            float* crow = C + (size_t)(r0 + half * 8) * ldc;
#pragma unroll
            for (int in = 0; in < 8; ++in) {
                float2 v = make_float2(acc[im][in][half * 2]     * scale,
                                       acc[im][in][half * 2 + 1] * scale);
                *(float2*)(crow + wn + in * 8 + tg * 2) = v;
            }
        }
    }
}

// q/k projections (n-tiles 0..3 -> q scaled, 4..7 -> k)
__global__ __launch_bounds__(128, 2) void gemm_qk_tc()
{
    const int nt = blockIdx.x;          // 0..7
    const int m0 = blockIdx.y * 128;
    float* Cp; int n0; float scale = 1.f;
    if (nt < 4) { Cp = g_q; n0 = nt * 128;       scale = 0.125f; }
    else        { Cp = g_k; n0 = (nt - 4) * 128; }
    mma_gemm_tile(g_xb + (size_t)m0 * KB2,
                  g_Wb + (size_t)nt * 128 * KB2,
                  Cp + (size_t)m0 * QKc + n0, QKc, scale);
}

// v/og projections (n-tiles 0..7 -> v, 8..15 -> og)
__global__ __launch_bounds__(128, 2) void gemm_vog_tc()
{
    const int nt = blockIdx.x;          // 0..15
    const int m0 = blockIdx.y * 128;
    float* Cp; int n0;
    if (nt < 8) { Cp = g_v;  n0 = nt * 128; }
    else        { Cp = g_og; n0 = (nt - 8) * 128; }
    mma_gemm_tile(g_xb + (size_t)m0 * KB2,
                  g_Wb + (size_t)(1024 + nt * 128) * KB2,
                  Cp + (size_t)m0 * Vc + n0, Vc, 1.f);
}

__global__ __launch_bounds__(128, 2) void gemm_out_tc(float* __restrict__ y)
{
    const int n0 = blockIdx.x * 128;
    const int m0 = blockIdx.y * 128;
    mma_gemm_tile(g_houtb + (size_t)m0 * KB2,
                  g_Woutb + (size_t)n0 * KB2,
                  y + (size_t)m0 * Dc + n0, Dc, 1.f);
}

// ---------------- fused fp32 -> bf16 hi/lo split ----------------------------
__device__ __forceinline__ void split2(float v, __nv_bfloat16& h, __nv_bfloat16& l) {
    h = __float2bfloat16(v);
    l = __float2bfloat16(v - __bfloat162float(h));
}
namespace {
constexpr int SEG0 =  524288;             // x     (float4 units)
constexpr int SEG1 = SEG0 + 131072;       // Wq
constexpr int SEG2 = SEG1 + 131072;       // Wk
constexpr int SEG3 = SEG2 + 262144;       // Wv
constexpr int SEG4 = SEG3 + 262144;       // Wog
constexpr int SEG5 = SEG4 + 262144;       // Wout -> total 1572864
}
__global__ void cvt_all2(const float* __restrict__ x,
                         const float* __restrict__ Wq, const float* __restrict__ Wk,
                         const float* __restrict__ Wv, const float* __restrict__ Wog,
                         const float* __restrict__ Wout)
{
    int idx = (blockIdx.x * 256 + threadIdx.x) * 2;
    const float* src; __nv_bfloat16* dst; int lidx;
    if      (idx < SEG0) { src = x;    dst = g_xb;              lidx = idx; }
    else if (idx < SEG1) { src = Wq;   dst = g_Wb;              lidx = idx - SEG0; }
    else if (idx < SEG2) { src = Wk;   dst = g_Wb +  512*KB2;   lidx = idx - SEG1; }
    else if (idx < SEG3) { src = Wv;   dst = g_Wb + 1024*KB2;   lidx = idx - SEG2; }
    else if (idx < SEG4) { src = Wog;  dst = g_Wb + 2048*KB2;   lidx = idx - SEG3; }
    else                 { src = Wout; dst = g_Woutb;           lidx = idx - SEG4; }
    int row = lidx >> 8;
    int c4  = lidx & 255;
    float4 v0 = ((const float4*)src)[lidx];
    float4 v1 = ((const float4*)src)[lidx + 1];
    float vf[8] = {v0.x, v0.y, v0.z, v0.w, v1.x, v1.y, v1.z, v1.w};
    uint32_t ph[4], pl[4];
#pragma unroll
    for (int p = 0; p < 4; ++p) {
        __nv_bfloat16 h0, l0, h1, l1;
        split2(vf[2*p],   h0, l0);
        split2(vf[2*p+1], h1, l1);
        __nv_bfloat162 hh = __halves2bfloat162(h0, h1);
        __nv_bfloat162 ll = __halves2bfloat162(l0, l1);
        ph[p] = *reinterpret_cast<uint32_t*>(&hh);
        pl[p] = *reinterpret_cast<uint32_t*>(&ll);
    }
    *(uint4*)(dst + (size_t)row * KB2 + c4 * 4)        = make_uint4(ph[0], ph[1], ph[2], ph[3]);
    *(uint4*)(dst + (size_t)row * KB2 + 1024 + c4 * 4) = make_uint4(pl[0], pl[1], pl[2], pl[3]);
}

// ---------------- gate GEMV: 4 outputs per warp -----------------------------
__global__ void gates_kernel(const float* __restrict__ x,
                             const float* __restrict__ Wi, const float* __restrict__ bi,
                             const float* __restrict__ Wf, const float* __restrict__ bf)
{
    const int wid  = blockIdx.x * 8 + (threadIdx.x >> 5);  // 0..8191
    const int lane = threadIdx.x & 31;
    const int row  = wid >> 2;
    const int g    = wid & 3;
    const float4* xr = (const float4*)(x + (size_t)row * Dc);
    const float4* wr[4];
#pragma unroll
    for (int j = 0; j < 4; ++j) {
        int o = g * 4 + j;
        const float* Wp = (o < 8) ? Wi : Wf;
        wr[j] = (const float4*)(Wp + (size_t)(o & 7) * Dc);
    }
    float acc[4] = {0.f, 0.f, 0.f, 0.f};
#pragma unroll 4
    for (int c = lane; c < Dc/4; c += 32) {
        float4 xv = __ldg(&xr[c]);
#pragma unroll
        for (int j = 0; j < 4; ++j) {
            float4 wv = __ldg(&wr[j][c]);
            acc[j] += xv.x*wv.x + xv.y*wv.y + xv.z*wv.z + xv.w*wv.w;
        }
    }
#pragma unroll
    for (int j = 0; j < 4; ++j)
#pragma unroll
        for (int off = 16; off > 0; off >>= 1)
            acc[j] += __shfl_xor_sync(0xffffffffu, acc[j], off);
    if (lane == 0) {
        int b = row >> 10, t = row & (Sc - 1);
#pragma unroll
        for (int j = 0; j < 4; ++j) {
            int o = g * 4 + j;
            int h = o & 7;
            float pre = acc[j] + ((o < 8) ? bi[h] : bf[h]);
            float cap = 15.f * tanhf(pre * (1.f/15.f));
            int idx = (b * NHc + h) * Sc + t;
            if (o >= 8) {
                float fl = (cap >= 0.f) ? -log1pf(expf(-cap))
                                        : (cap - log1pf(expf(cap)));
                g_flog[idx] = fl;
            } else {
                g_icap[idx] = cap;
            }
        }
    }
}

// ---------------- parallel max-plus scan (per (b,h)) ------------------------
__global__ __launch_bounds__(128) void scan_kernel()
{
    __shared__ float wA[4], wB[4];
    const int bh = blockIdx.x, tid = threadIdx.x;
    const int lane = tid & 31, w = tid >> 5;
    const float* fl = g_flog + bh * Sc + tid * 8;
    const float* ic = g_icap + bh * Sc + tid * 8;
    float a[8], b[8];
#pragma unroll
    for (int j = 0; j < 8; ++j) { a[j] = fl[j]; b[j] = ic[j]; }
    float A = 0.f, B = -1e30f;
#pragma unroll
    for (int j = 0; j < 8; ++j) { B = fmaxf(B + a[j], b[j]); A += a[j]; }
#pragma unroll
    for (int off = 1; off < 32; off <<= 1) {
        float A2 = __shfl_up_sync(0xffffffffu, A, off);
        float B2 = __shfl_up_sync(0xffffffffu, B, off);
        if (lane >= off) { B = fmaxf(B2 + A, B); A = A2 + A; }
    }
    if (lane == 31) { wA[w] = A; wB[w] = B; }
    __syncthreads();
    float pA = 0.f, pB = -1e30f;
    for (int ww = 0; ww < w; ++ww) { pB = fmaxf(pB + wA[ww], wB[ww]); pA += wA[ww]; }
    float eA = __shfl_up_sync(0xffffffffu, A, 1);
    float eB = __shfl_up_sync(0xffffffffu, B, 1);
    if (lane == 0) { eA = 0.f; eB = -1e30f; }
    float EB = fmaxf(pB + eA, eB);
    float EA = pA + eA;
    float m = fmaxf(EA, EB);
    const int base = bh * Sc + tid * 8;
#pragma unroll
    for (int j = 0; j < 8; ++j) {
        float mp = m;
        m = fmaxf(a[j] + mp, b[j]);
        g_fact[base + j] = expf(a[j] + mp - m);
        g_iact[base + j] = expf(b[j] - m);
        g_em  [base + j] = expf(-m);
    }
}

// ---------------- n-scan + denominator: one channel per thread -------------
__global__ __launch_bounds__(64) void nscan_kernel()
{
    __shared__ float sP[32][65];
    const int bh = blockIdx.x;
    const int b = bh >> 3, h = bh & 7;
    const int d = threadIdx.x;
    const int warp = d >> 5, lane = d & 31;
    const float* kp = g_k + (size_t)b*Sc*QKc + h*DQKc + d;
    const float* qp = g_q + (size_t)b*Sc*QKc + h*DQKc + d;
    const float* fa = g_fact + bh*Sc;
    const float* ia = g_iact + bh*Sc;
    float n = 0.f;
    for (int tile = 0; tile < Sc/32; ++tile) {
        const int t0 = tile * 32;
#pragma unroll 8
        for (int s = 0; s < 32; ++s) {
            int t = t0 + s;
            float kv = __ldg(kp + (size_t)t * QKc);
            float qv = __ldg(qp + (size_t)t * QKc);
            n = fa[t]*n + ia[t]*kv;
            sP[s][d] = qv * n;
        }
        __syncthreads();
#pragma unroll
        for (int i = 0; i < 16; ++i) {
            int tt = warp * 16 + i;
            float v = sP[tt][lane] + sP[tt][lane + 32];
#pragma unroll
            for (int off = 16; off > 0; off >>= 1)
                v += __shfl_xor_sync(0xffffffffu, v, off);
            if (lane == 0) {
                int t = t0 + tt;
                float den = fmaxf(fabsf(v), g_em[bh*Sc + t]) + 1e-6f;
                g_invden[bh*Sc + t] = 1.f / den;
            }
        }
        __syncthreads();
    }
}

// ---------------- main C-state recurrence -----------------------------------
__global__ __launch_bounds__(256) void recur_kernel()
{
    __shared__ float sK[32][64];
    __shared__ float sQ[32][64];
    __shared__ float sV[32][16];
    __shared__ float sS[3][32];
    const int vb = blockIdx.x;
    const int bh = blockIdx.y;
    const int b = bh >> 3, h = bh & 7;
    const int tid = threadIdx.x;
    const int vi = tid >> 4;
    const int dc = tid & 15;

    float C[4] = {0.f, 0.f, 0.f, 0.f};
    float4 rk[2], rq[2], rv;
    float rs = 0.f;

    auto g_load = [&] (int t0) {
#pragma unroll
        for (int u = 0; u < 2; ++u) {
            int id = tid + 256*u;
            int r = id >> 4, c = id & 15;
            int gb = (b*Sc + t0 + r) * QKc + h * DQKc + c * 4;
            rk[u] = *(const float4*)&g_k[gb];
            rq[u] = *(const float4*)&g_q[gb];
        }
        if (tid < 128) {
            int r = tid >> 2, c = tid & 3;
            rv = *(const float4*)&g_v[(b*Sc + t0 + r) * Vc + h * DHVc + vb*16 + c*4];
        } else if (tid < 224) {
            int which = (tid - 128) >> 5, s = (tid - 128) & 31;
            const float* sp = (which == 0) ? g_fact : ((which == 1) ? g_iact : g_invden);
            rs = sp[bh*Sc + t0 + s];
        }
    };
    auto s_store = [&] () {
#pragma unroll
        for (int u = 0; u < 2; ++u) {
            int id = tid + 256*u;
            int r = id >> 4, c = id & 15;
            *(float4*)&sK[r][c*4] = rk[u];
            *(float4*)&sQ[r][c*4] = rq[u];
        }
        if (tid < 128) {
            int r = tid >> 2, c = tid & 3;
            *(float4*)&sV[r][c*4] = rv;
        } else if (tid < 224) {
            sS[(tid-128)>>5][(tid-128)&31] = rs;
        }
    };

    g_load(0);
    s_store();
    __syncthreads();

    const int NT = Sc / 32;
    for (int tile = 0; tile < NT; ++tile) {
        if (tile + 1 < NT) g_load((tile + 1) * 32);
#pragma unroll 4
        for (int s = 0; s < 32; ++s) {
            float fa  = sS[0][s];
            float iv  = sS[1][s] * sV[s][vi];
            float idn = sS[2][s];
            float4 k0 = *(const float4*)&sK[s][dc*4];
            float4 q0 = *(const float4*)&sQ[s][dc*4];
            C[0] = fa*C[0] + k0.x*iv;
            C[1] = fa*C[1] + k0.y*iv;
            C[2] = fa*C[2] + k0.z*iv;
            C[3] = fa*C[3] + k0.w*iv;
            float p = q0.x*C[0] + q0.y*C[1] + q0.z*C[2] + q0.w*C[3];
            p += __shfl_xor_sync(0xffffffffu, p, 1);
            p += __shfl_xor_sync(0xffffffffu, p, 2);
            p += __shfl_xor_sync(0xffffffffu, p, 4);
            p += __shfl_xor_sync(0xffffffffu, p, 8);
            if (dc == 0) {
                int t = tile*32 + s;
                g_h[(b*Sc + t) * Vc + h*DHVc + vb*16 + vi] = p * idn;
            }
        }
        if (tile + 1 < NT) {
            __syncthreads();
            s_store();
            __syncthreads();
        }
    }
}

// ------ per-head layernorm * gamma * sigmoid(o_pre) -> bf16 hi/lo pairs ----
__global__ void ln_gate_kernel(const float* __restrict__ gamma)
{
    const int row  = blockIdx.x;
    const int hd   = threadIdx.x >> 5;
    const int lane = threadIdx.x & 31;
    const int base = row * Vc + hd * DHVc + lane * 4;
    float4 hv = *(const float4*)&g_h[base];
    float sm = hv.x + hv.y + hv.z + hv.w;
#pragma unroll
    for (int off = 16; off > 0; off >>= 1)
        sm += __shfl_xor_sync(0xffffffffu, sm, off);
    float mu = sm * (1.f/128.f);
    float dx = hv.x - mu, dy = hv.y - mu, dz = hv.z - mu, dw = hv.w - mu;
    float sq = dx*dx + dy*dy + dz*dz + dw*dw;
#pragma unroll
    for (int off = 16; off > 0; off >>= 1)
        sq += __shfl_xor_sync(0xffffffffu, sq, off);
    float rstd = rsqrtf(sq * (1.f/128.f) + 1e-6f);
    float4 gm = *(const float4*)&gamma[hd * DHVc + lane * 4];
    float4 og = *(const float4*)&g_og[base];
    float ox = dx * rstd * gm.x / (1.f + expf(-og.x));
    float oy = dy * rstd * gm.y / (1.f + expf(-og.y));
    float oz = dz * rstd * gm.z / (1.f + expf(-og.z));
    float ow = dw * rstd * gm.w / (1.f + expf(-og.w));
    __nv_bfloat16 h0,h1,h2,h3,l0,l1,l2,l3;
    split2(ox,h0,l0); split2(oy,h1,l1); split2(oz,h2,l2); split2(ow,h3,l3);
    const int col = hd * DHVc + lane * 4;
    __nv_bfloat162* dh = (__nv_bfloat162*)(g_houtb + (size_t)row * KB2 + col);
    dh[0] = __halves2bfloat162(h0, h1);
    dh[1] = __halves2bfloat162(h2, h3);
    __nv_bfloat162* dl = (__nv_bfloat162*)(g_houtb + (size_t)row * KB2 + 1024 + col);
    dl[0] = __halves2bfloat162(l0, l1);
    dl[1] = __halves2bfloat162(l2, l3);
}

// ---------------- launch ----------------------------------------------------
extern "C" void kernel_launch(void* const* d_in, const int* in_sizes, int n_in,
                              void* d_out, int out_size)
{
    const float* x     = (const float*)d_in[0];
    const float* Wq    = (const float*)d_in[1];
    const float* Wk    = (const float*)d_in[2];
    const float* Wv    = (const float*)d_in[3];
    const float* Wog   = (const float*)d_in[4];
    const float* Wi    = (const float*)d_in[5];
    const float* bi    = (const float*)d_in[6];
    const float* Wf    = (const float*)d_in[7];
    const float* bf    = (const float*)d_in[8];
    const float* gamma = (const float*)d_in[9];
    const float* Wout  = (const float*)d_in[10];
    float* y = (float*)d_out;

    cudaStream_t s2;
    cudaStreamCreateWithFlags(&s2, cudaStreamNonBlocking);
    cudaEvent_t e1, e_qk, e_ns;
    cudaEventCreateWithFlags(&e1,   cudaEventDisableTiming);
    cudaEventCreateWithFlags(&e_qk, cudaEventDisableTiming);
    cudaEventCreateWithFlags(&e_ns, cudaEventDisableTiming);

    // side stream: gates + m-scan (depend only on raw x)
    cudaEventRecord(e1, 0);
    cudaStreamWaitEvent(s2, e1, 0);
    gates_kernel<<<1024, 256, 0, s2>>>(x, Wi, bi, Wf, bf);
    scan_kernel<<<16, 128, 0, s2>>>();

    // main: conversions + q/k GEMM
    cvt_all2<<<3072, 256>>>(x, Wq, Wk, Wv, Wog, Wout);
    gemm_qk_tc<<<dim3(8, 16), 128>>>();
    cudaEventRecord(e_qk, 0);

    // side stream: nscan (needs q,k + scan outputs), overlapping v/og GEMM
    cudaStreamWaitEvent(s2, e_qk, 0);
    nscan_kernel<<<16, 64, 0, s2>>>();
    cudaEventRecord(e_ns, s2);

    // main: v/og GEMM concurrent with nscan
    gemm_vog_tc<<<dim3(16, 16), 128>>>();

    // join: recur needs v, fact/iact/invden
    cudaStreamWaitEvent(0, e_ns, 0);
    recur_kernel<<<dim3(8, 16), 256>>>();
    ln_gate_kernel<<<Bc * Sc, 256>>>(gamma);
    gemm_out_tc<<<dim3(8, 16), 128>>>(y);

    cudaEventDestroy(e1);
    cudaEventDestroy(e_qk);
    cudaEventDestroy(e_ns);
    cudaStreamDestroy(s2);
}